// round 8
// baseline (speedup 1.0000x reference)
#include <cuda_runtime.h>
#include <cuda_bf16.h>
#include <cstdint>

#define C 128
#define E_EDGES 1000000
#define TILE 128
#define NTILES ((E_EDGES + TILE - 1) / TILE)   // 7813 (last tile has 64 rows)
#define BN_EPS 1e-5f
#define PITCHB 272   // bytes per bf16 tile row (136 halves: 128 data + 8 pad)

// ---------------- SMEM byte layout (dynamic) ----------------
// A double-buffered: buf b at b*69632  (hi at +0, lo at +34816), 128 rows each
#define SM_ABUF(b) ((b) * 69632)
#define SM_ALO_OFF 34816
#define SM_BH    139264   // B hi bf16 [k=128][n=136] 34816 B
#define SM_BL    174080   // B lo                     34816 B
#define SM_BIAS  208896   // float[128]
#define SM_SCALE 209408   // float[128]
#define SM_SHIFT 209920   // float[128]
#define SM_RED1  210432   // float[128]
#define SM_RED2  210944   // float[128]
#define SM_TOTAL 211456

// 512 MB scratch for h1pre (pass1 -> pass2) then h2pre (pass2 -> out), in place.
__device__ float g_h[(size_t)E_EDGES * C];
__device__ __align__(16) float g_sum1[C], g_sq1[C], g_sum2[C], g_sq2[C];
__device__ __align__(16) float g_a1[C], g_c1[C], g_a2[C], g_c2[C];
__device__ int g_is64;

// ---------------- helpers ----------------
__device__ __forceinline__ uint32_t smem_u32(const void* p) {
    uint32_t a;
    asm("{ .reg .u64 t; cvta.to.shared.u64 t, %1; cvt.u32.u64 %0, t; }" : "=r"(a) : "l"(p));
    return a;
}
__device__ __forceinline__ void ldsm4(uint32_t* r, uint32_t addr) {
    asm volatile("ldmatrix.sync.aligned.m8n8.x4.shared.b16 {%0,%1,%2,%3}, [%4];"
                 : "=r"(r[0]), "=r"(r[1]), "=r"(r[2]), "=r"(r[3]) : "r"(addr));
}
__device__ __forceinline__ void ldsm4t(uint32_t* r, uint32_t addr) {
    asm volatile("ldmatrix.sync.aligned.m8n8.x4.trans.shared.b16 {%0,%1,%2,%3}, [%4];"
                 : "=r"(r[0]), "=r"(r[1]), "=r"(r[2]), "=r"(r[3]) : "r"(addr));
}
__device__ __forceinline__ void mma16816(float* d, const uint32_t* a, const uint32_t* b) {
    asm volatile(
        "mma.sync.aligned.m16n8k16.row.col.f32.bf16.bf16.f32 "
        "{%0,%1,%2,%3}, {%4,%5,%6,%7}, {%8,%9}, {%0,%1,%2,%3};"
        : "+f"(d[0]), "+f"(d[1]), "+f"(d[2]), "+f"(d[3])
        : "r"(a[0]), "r"(a[1]), "r"(a[2]), "r"(a[3]), "r"(b[0]), "r"(b[1]));
}
__device__ __forceinline__ void split_bf16(float v, __nv_bfloat16& h, __nv_bfloat16& l) {
    h = __float2bfloat16_rn(v);
    l = __float2bfloat16_rn(v - __bfloat162float(h));
}
__device__ __forceinline__ uint32_t pack_bf(__nv_bfloat16 a, __nv_bfloat16 b) {
    return ((uint32_t)__bfloat16_as_ushort(b) << 16) | __bfloat16_as_ushort(a);
}

__global__ void k_zero(const unsigned* __restrict__ ew) {
    int t = threadIdx.x;
    if (t < C) { g_sum1[t] = 0.f; g_sq1[t] = 0.f; g_sum2[t] = 0.f; g_sq2[t] = 0.f; }
    if (t == 0) {
        // int64 edge data (non-negative < 2^31) has every odd 32-bit word == 0
        int all0 = 1;
        #pragma unroll
        for (int k = 0; k < 8; k++) all0 &= (ew[2 * k + 1] == 0u);
        g_is64 = all0;
    }
}

// PASS 1: A = x[i]*x[j] (gather), B = w1, D -> h1pre -> g_h, stats1
// PASS 2: A = relu(a1*g_h + c1),  B = w2, D -> h2pre -> g_h, stats2
template <int PASS>
__global__ __launch_bounds__(256, 1) void k_pass_mma(
    const float* __restrict__ x, const void* __restrict__ edges_raw,
    const float* __restrict__ w, const float* __restrict__ bias)
{
    extern __shared__ char sm[];
    const uint32_t sb = smem_u32(sm);
    const int tid = threadIdx.x;
    const int wid = tid >> 5;
    const int lid = tid & 31;
    const int gid = lid >> 2;
    const int tig = lid & 3;
    const int m0 = (wid & 3) * 32;    // warp's 32 rows (4 m-bands)
    const int n0 = (wid >> 2) * 64;   // warp's 64 cols (2 n-bands)

    float* sBias  = (float*)(sm + SM_BIAS);
    float* sScale = (float*)(sm + SM_SCALE);
    float* sShift = (float*)(sm + SM_SHIFT);
    float* sRed1  = (float*)(sm + SM_RED1);
    float* sRed2  = (float*)(sm + SM_RED2);

    if (tid < C) {
        sBias[tid] = bias[tid];
        sRed1[tid] = 0.f; sRed2[tid] = 0.f;
        if (PASS == 2) { sScale[tid] = g_a1[tid]; sShift[tid] = g_c1[tid]; }
    }
    // ---- W -> Bh/Bl, natural [k][n] layout, padded pitch ----
    for (int idx = tid; idx < C * C; idx += 256) {
        int k = idx >> 7, n = idx & 127;
        __nv_bfloat16 hb, lb;
        split_bf16(w[idx], hb, lb);
        uint32_t off = (uint32_t)(k * PITCHB + n * 2);
        *(__nv_bfloat16*)(sm + SM_BH + off) = hb;
        *(__nv_bfloat16*)(sm + SM_BL + off) = lb;
    }
    __syncthreads();

    const int is64 = g_is64;
    const long long* e64 = (const long long*)edges_raw;
    const int*       e32 = (const int*)edges_raw;
    const float4*    x4  = (const float4*)x;

    const int rowb = wid;         // prefetch rows rowb + 8i, i=0..15
    const int cseg = tid & 31;    // float4 column group

    float4 sc4 = make_float4(0.f,0.f,0.f,0.f), sh4 = sc4;
    if (PASS == 2) {
        sc4 = *(const float4*)&sScale[cseg * 4];
        sh4 = *(const float4*)&sShift[cseg * 4];
    }

    float2 s1v[8], s2v[8];
    #pragma unroll
    for (int q = 0; q < 8; q++) { s1v[q] = make_float2(0.f,0.f); s2v[q] = make_float2(0.f,0.f); }

    float4 p[16];

    // ---- prefetch helper (inlined twice below) ----
    #define PREFETCH(ett)                                                          \
        _Pragma("unroll")                                                          \
        for (int i = 0; i < 16; i++) {                                             \
            int e = (ett) * TILE + rowb + 8 * i;                                   \
            if (e < E_EDGES) {                                                     \
                if (PASS == 1) {                                                   \
                    int ei, ej;                                                    \
                    if (is64) { ei = (int)e64[e]; ej = (int)e64[(size_t)E_EDGES + e]; } \
                    else      { ei = e32[e];      ej = e32[(size_t)E_EDGES + e]; } \
                    float4 a = x4[(size_t)ei * 32 + cseg];                         \
                    float4 b = x4[(size_t)ej * 32 + cseg];                         \
                    p[i] = make_float4(a.x*b.x, a.y*b.y, a.z*b.z, a.w*b.w);        \
                } else {                                                           \
                    p[i] = *(const float4*)&g_h[(size_t)e * C + cseg * 4];         \
                }                                                                  \
            } else p[i] = make_float4(0.f, 0.f, 0.f, 0.f);                         \
        }

    #define STORE_A(bufbase)                                                       \
        _Pragma("unroll")                                                          \
        for (int i = 0; i < 16; i++) {                                             \
            float4 v = p[i];                                                       \
            if (PASS == 2) {                                                       \
                v.x = fmaxf(fmaf(v.x, sc4.x, sh4.x), 0.f);                         \
                v.y = fmaxf(fmaf(v.y, sc4.y, sh4.y), 0.f);                         \
                v.z = fmaxf(fmaf(v.z, sc4.z, sh4.z), 0.f);                         \
                v.w = fmaxf(fmaf(v.w, sc4.w, sh4.w), 0.f);                         \
            }                                                                      \
            __nv_bfloat16 h0,h1,h2,h3,l0,l1,l2,l3;                                 \
            split_bf16(v.x,h0,l0); split_bf16(v.y,h1,l1);                          \
            split_bf16(v.z,h2,l2); split_bf16(v.w,h3,l3);                          \
            uint32_t off = (uint32_t)((rowb + 8*i) * PITCHB + cseg * 8);           \
            *(uint2*)(sm + (bufbase) + off) = make_uint2(pack_bf(h0,h1), pack_bf(h2,h3)); \
            *(uint2*)(sm + (bufbase) + SM_ALO_OFF + off) = make_uint2(pack_bf(l0,l1), pack_bf(l2,l3)); \
        }

    // ---- prologue: fill buffer 0 with tile t0 ----
    const int t0 = blockIdx.x;
    PREFETCH(t0);
    STORE_A(SM_ABUF(0));
    __syncthreads();

    int cur = 0;
    for (int t = t0; t < NTILES; t += gridDim.x) {
        const int e0 = t * TILE;
        const int tn = t + gridDim.x;

        // ---- prefetch next tile (overlaps the MMA below) ----
        if (tn < NTILES) { PREFETCH(tn); }

        // ---- MMA on A[cur]: D = Ah*Bh + Al*Bh + Ah*Bl (32x64 warp tile) ----
        const uint32_t aH = sb + SM_ABUF(cur);
        const uint32_t aL = aH + SM_ALO_OFF;

        float acc[2][8][4];
        #pragma unroll
        for (int mt = 0; mt < 2; mt++)
            #pragma unroll
            for (int q = 0; q < 8; q++)
                #pragma unroll
                for (int r = 0; r < 4; r++) acc[mt][q][r] = 0.f;

        #pragma unroll
        for (int ks = 0; ks < 8; ks++) {
            uint32_t ah[2][4], al[2][4];
            #pragma unroll
            for (int mt = 0; mt < 2; mt++) {
                uint32_t off = (uint32_t)((m0 + mt*16 + (lid & 15)) * PITCHB
                                          + (ks*16 + (lid >> 4) * 8) * 2);
                ldsm4(ah[mt], aH + off);
                ldsm4(al[mt], aL + off);
            }
            #pragma unroll
            for (int nb = 0; nb < 4; nb++) {
                uint32_t boff = (uint32_t)(
                    (ks*16 + (lid & 7) + ((lid >> 3) & 1) * 8) * PITCHB
                    + (n0 + nb*16 + (lid >> 4) * 8) * 2);
                uint32_t bh[4], bl[4];
                ldsm4t(bh, sb + SM_BH + boff);
                ldsm4t(bl, sb + SM_BL + boff);
                // interleave so same-acc mmas are >=4 apart
                mma16816(acc[0][2*nb],   ah[0], bh);
                mma16816(acc[1][2*nb],   ah[1], bh);
                mma16816(acc[0][2*nb+1], ah[0], bh+2);
                mma16816(acc[1][2*nb+1], ah[1], bh+2);
                mma16816(acc[0][2*nb],   al[0], bh);
                mma16816(acc[1][2*nb],   al[1], bh);
                mma16816(acc[0][2*nb+1], al[0], bh+2);
                mma16816(acc[1][2*nb+1], al[1], bh+2);
                mma16816(acc[0][2*nb],   ah[0], bl);
                mma16816(acc[1][2*nb],   ah[1], bl);
                mma16816(acc[0][2*nb+1], ah[0], bl+2);
                mma16816(acc[1][2*nb+1], ah[1], bl+2);
            }
        }

        // ---- epilogue: +bias, direct STG to scratch, register stats ----
        #pragma unroll
        for (int nb = 0; nb < 4; nb++) {
            #pragma unroll
            for (int h = 0; h < 2; h++) {
                const int q = nb*2 + h;
                const int c0 = n0 + nb*16 + h*8 + 2*tig;
                float2 bb = *(const float2*)&sBias[c0];
                #pragma unroll
                for (int mt = 0; mt < 2; mt++) {
                    int r = m0 + mt * 16 + gid;
                    int e = e0 + r;
                    float2 v0 = make_float2(acc[mt][q][0] + bb.x, acc[mt][q][1] + bb.y);
                    float2 v1 = make_float2(acc[mt][q][2] + bb.x, acc[mt][q][3] + bb.y);
                    if (e < E_EDGES) {
                        *(float2*)&g_h[(size_t)e * C + c0] = v0;
                        s1v[q].x += v0.x; s1v[q].y += v0.y;
                        s2v[q].x += v0.x*v0.x; s2v[q].y += v0.y*v0.y;
                    }
                    if (e + 8 < E_EDGES) {
                        *(float2*)&g_h[(size_t)(e + 8) * C + c0] = v1;
                        s1v[q].x += v1.x; s1v[q].y += v1.y;
                        s2v[q].x += v1.x*v1.x; s2v[q].y += v1.y*v1.y;
                    }
                }
            }
        }

        // ---- write next tile's A into the other buffer ----
        if (tn < NTILES) { STORE_A(SM_ABUF(cur ^ 1)); }
        __syncthreads();
        cur ^= 1;
    }

    // ---- stats: reduce over gid (xor-shuffles), then shared, then global ----
    #pragma unroll
    for (int q = 0; q < 8; q++) {
        #pragma unroll
        for (int msk = 4; msk <= 16; msk <<= 1) {
            s1v[q].x += __shfl_xor_sync(0xffffffffu, s1v[q].x, msk);
            s1v[q].y += __shfl_xor_sync(0xffffffffu, s1v[q].y, msk);
            s2v[q].x += __shfl_xor_sync(0xffffffffu, s2v[q].x, msk);
            s2v[q].y += __shfl_xor_sync(0xffffffffu, s2v[q].y, msk);
        }
    }
    if (gid == 0) {
        #pragma unroll
        for (int q = 0; q < 8; q++) {
            int c0 = n0 + (q >> 1) * 16 + (q & 1) * 8 + 2 * tig;
            atomicAdd(&sRed1[c0], s1v[q].x);  atomicAdd(&sRed1[c0+1], s1v[q].y);
            atomicAdd(&sRed2[c0], s2v[q].x);  atomicAdd(&sRed2[c0+1], s2v[q].y);
        }
    }
    __syncthreads();
    if (tid < C) {
        atomicAdd((PASS == 1 ? g_sum1 : g_sum2) + tid, sRed1[tid]);
        atomicAdd((PASS == 1 ? g_sq1 : g_sq2) + tid, sRed2[tid]);
    }
}

__global__ void k_fin(const float* __restrict__ g, const float* __restrict__ be, int which) {
    int c = threadIdx.x;
    float sum = which ? g_sum2[c] : g_sum1[c];
    float sq  = which ? g_sq2[c]  : g_sq1[c];
    float mean = sum * (1.f / E_EDGES);
    float var  = sq * (1.f / E_EDGES) - mean * mean;
    float a = g[c] * rsqrtf(var + BN_EPS);
    float cc = be[c] - mean * a;
    if (which) { g_a2[c] = a; g_c2[c] = cc; }
    else       { g_a1[c] = a; g_c1[c] = cc; }
}

__global__ __launch_bounds__(256) void k_out(const float* __restrict__ wc,
                                             const float* __restrict__ bc,
                                             float* __restrict__ out)
{
    const int lane = threadIdx.x & 31;
    const int warp = threadIdx.x >> 5;
    const int nwarp = gridDim.x * 8;
    const int wg = blockIdx.x * 8 + warp;

    float4 a2 = *(const float4*)&g_a2[lane * 4];
    float4 c2 = *(const float4*)&g_c2[lane * 4];
    float4 wv = *(const float4*)&wc[lane * 4];
    float b = bc[0];

    for (size_t e = wg; e < E_EDGES; e += nwarp) {
        float4 v = *(const float4*)&g_h[e * C + lane * 4];
        float r = fmaxf(fmaf(v.x, a2.x, c2.x), 0.f) * wv.x
                + fmaxf(fmaf(v.y, a2.y, c2.y), 0.f) * wv.y
                + fmaxf(fmaf(v.z, a2.z, c2.z), 0.f) * wv.z
                + fmaxf(fmaf(v.w, a2.w, c2.w), 0.f) * wv.w;
        #pragma unroll
        for (int s = 16; s > 0; s >>= 1) r += __shfl_xor_sync(0xffffffffu, r, s);
        if (lane == 0) out[e] = r + b;
    }
}

extern "C" void kernel_launch(void* const* d_in, const int* in_sizes, int n_in,
                              void* d_out, int out_size) {
    const float* x     = (const float*)d_in[0];
    const void*  edges = d_in[1];
    const float* w1    = (const float*)d_in[2];
    const float* b1    = (const float*)d_in[3];
    const float* g1    = (const float*)d_in[4];
    const float* be1   = (const float*)d_in[5];
    const float* w2    = (const float*)d_in[6];
    const float* b2    = (const float*)d_in[7];
    const float* g2    = (const float*)d_in[8];
    const float* be2   = (const float*)d_in[9];
    const float* wc    = (const float*)d_in[10];
    const float* bc    = (const float*)d_in[11];
    float* out = (float*)d_out;
    (void)in_sizes; (void)n_in; (void)out_size;

    cudaFuncSetAttribute(k_pass_mma<1>, cudaFuncAttributeMaxDynamicSharedMemorySize, SM_TOTAL);
    cudaFuncSetAttribute(k_pass_mma<2>, cudaFuncAttributeMaxDynamicSharedMemorySize, SM_TOTAL);

    k_zero<<<1, 128>>>((const unsigned*)edges);
    k_pass_mma<1><<<148, 256, SM_TOTAL>>>(x, edges, w1, b1);
    k_fin<<<1, 128>>>(g1, be1, 0);
    k_pass_mma<2><<<148, 256, SM_TOTAL>>>(x, edges, w2, b2);
    k_fin<<<1, 128>>>(g2, be2, 1);
    k_out<<<2048, 256>>>(wc, bc, out);
}

// round 10
// speedup vs baseline: 1.5255x; 1.5255x over previous
#include <cuda_runtime.h>
#include <cuda_bf16.h>
#include <cstdint>

#define C 128
#define E_EDGES 1000000
#define TILE 64
#define NTILES (E_EDGES / TILE)   // 15625 exact
#define BN_EPS 1e-5f
#define PITCHB 272   // bytes per bf16 tile row (136 halves: 128 data + 8 pad)

// ---------------- SMEM byte layout (dynamic), TILE=64 ----------------
#define SM_AH    0        // A hi bf16 [64 x 136]     17408 B
#define SM_AL    17408    // A lo bf16                17408 B
#define SM_BH    34816    // B hi bf16 [k=128][n=136] 34816 B
#define SM_BL    69632    // B lo                     34816 B
#define SM_BIAS  104448   // float[128]
#define SM_SCALE 104960   // float[128]
#define SM_SHIFT 105472   // float[128]
#define SM_I     105984   // int[2][64] double-buffered
#define SM_J     106496   // int[2][64]
#define SM_RED1  107008   // float[128]
#define SM_RED2  107520   // float[128]
#define SM_TOTAL 108032

// 512 MB scratch for h1pre (pass1 -> pass2) then h2pre (pass2 -> out), in place.
__device__ float g_h[(size_t)E_EDGES * C];
__device__ __align__(16) float g_sum1[C], g_sq1[C], g_sum2[C], g_sq2[C];
__device__ __align__(16) float g_a1[C], g_c1[C], g_a2[C], g_c2[C];
__device__ int g_is64;

// ---------------- helpers ----------------
__device__ __forceinline__ uint32_t smem_u32(const void* p) {
    uint32_t a;
    asm("{ .reg .u64 t; cvta.to.shared.u64 t, %1; cvt.u32.u64 %0, t; }" : "=r"(a) : "l"(p));
    return a;
}
__device__ __forceinline__ void ldsm4(uint32_t* r, uint32_t addr) {
    asm volatile("ldmatrix.sync.aligned.m8n8.x4.shared.b16 {%0,%1,%2,%3}, [%4];"
                 : "=r"(r[0]), "=r"(r[1]), "=r"(r[2]), "=r"(r[3]) : "r"(addr));
}
__device__ __forceinline__ void ldsm4t(uint32_t* r, uint32_t addr) {
    asm volatile("ldmatrix.sync.aligned.m8n8.x4.trans.shared.b16 {%0,%1,%2,%3}, [%4];"
                 : "=r"(r[0]), "=r"(r[1]), "=r"(r[2]), "=r"(r[3]) : "r"(addr));
}
__device__ __forceinline__ void mma16816(float* d, const uint32_t* a, const uint32_t* b) {
    asm volatile(
        "mma.sync.aligned.m16n8k16.row.col.f32.bf16.bf16.f32 "
        "{%0,%1,%2,%3}, {%4,%5,%6,%7}, {%8,%9}, {%0,%1,%2,%3};"
        : "+f"(d[0]), "+f"(d[1]), "+f"(d[2]), "+f"(d[3])
        : "r"(a[0]), "r"(a[1]), "r"(a[2]), "r"(a[3]), "r"(b[0]), "r"(b[1]));
}
__device__ __forceinline__ void split_bf16(float v, __nv_bfloat16& h, __nv_bfloat16& l) {
    h = __float2bfloat16_rn(v);
    l = __float2bfloat16_rn(v - __bfloat162float(h));
}
__device__ __forceinline__ uint32_t pack_bf(__nv_bfloat16 a, __nv_bfloat16 b) {
    return ((uint32_t)__bfloat16_as_ushort(b) << 16) | __bfloat16_as_ushort(a);
}

__global__ void k_zero(const unsigned* __restrict__ ew) {
    int t = threadIdx.x;
    if (t < C) { g_sum1[t] = 0.f; g_sq1[t] = 0.f; g_sum2[t] = 0.f; g_sq2[t] = 0.f; }
    if (t == 0) {
        // int64 edge data (non-negative < 2^31) has every odd 32-bit word == 0
        int all0 = 1;
        #pragma unroll
        for (int k = 0; k < 8; k++) all0 &= (ew[2 * k + 1] == 0u);
        g_is64 = all0;
    }
}

// PASS 1: A = x[i]*x[j] (gather), B = w1, D -> h1pre -> g_h, stats1
// PASS 2: A = relu(a1*g_h + c1),  B = w2, D -> h2pre -> g_h, stats2
template <int PASS>
__global__ __launch_bounds__(256, 2) void k_pass_mma(
    const float* __restrict__ x, const void* __restrict__ edges_raw,
    const float* __restrict__ w, const float* __restrict__ bias)
{
    extern __shared__ char sm[];
    const uint32_t sb = smem_u32(sm);
    const int tid = threadIdx.x;
    const int wid = tid >> 5;
    const int lid = tid & 31;
    const int gid = lid >> 2;
    const int tig = lid & 3;
    const int m0 = (wid & 1) * 32;    // warp's 32 rows
    const int n0 = (wid >> 1) * 32;   // warp's 32 cols

    float* sBias  = (float*)(sm + SM_BIAS);
    float* sScale = (float*)(sm + SM_SCALE);
    float* sShift = (float*)(sm + SM_SHIFT);
    int*   sI     = (int*)(sm + SM_I);
    int*   sJ     = (int*)(sm + SM_J);
    float* sRed1  = (float*)(sm + SM_RED1);
    float* sRed2  = (float*)(sm + SM_RED2);

    if (tid < C) {
        sBias[tid] = bias[tid];
        sRed1[tid] = 0.f; sRed2[tid] = 0.f;
        if (PASS == 2) { sScale[tid] = g_a1[tid]; sShift[tid] = g_c1[tid]; }
    }
    // ---- W -> Bh/Bl, natural [k][n] layout, padded pitch ----
    for (int idx = tid; idx < C * C; idx += 256) {
        int k = idx >> 7, n = idx & 127;
        __nv_bfloat16 hb, lb;
        split_bf16(w[idx], hb, lb);
        uint32_t off = (uint32_t)(k * PITCHB + n * 2);
        *(__nv_bfloat16*)(sm + SM_BH + off) = hb;
        *(__nv_bfloat16*)(sm + SM_BL + off) = lb;
    }
    __syncthreads();

    const int is64 = g_is64;
    const long long* e64 = (const long long*)edges_raw;
    const int*       e32 = (const int*)edges_raw;
    const float4*    x4  = (const float4*)x;

    const int rowb = tid >> 5;    // row base 0..7 (rows rowb + 8i)
    const int cseg = tid & 31;    // float4 column group

    float4 sc4 = make_float4(0.f,0.f,0.f,0.f), sh4 = sc4;
    if (PASS == 2) {
        sc4 = *(const float4*)&sScale[cseg * 4];
        sh4 = *(const float4*)&sShift[cseg * 4];
    }

    float2 s1v[4], s2v[4];
    #pragma unroll
    for (int q = 0; q < 4; q++) { s1v[q] = make_float2(0.f,0.f); s2v[q] = make_float2(0.f,0.f); }

    // ---- prologue: prefetch tile t0 into registers ----
    float4 p[8];
    int buf = 0;
    const int t0 = blockIdx.x;
    if (PASS == 1) {
        if (t0 < NTILES && tid < TILE) {
            int e = t0 * TILE + tid;
            if (is64) { sI[tid] = (int)e64[e]; sJ[tid] = (int)e64[(size_t)E_EDGES + e]; }
            else      { sI[tid] = e32[e];      sJ[tid] = e32[(size_t)E_EDGES + e]; }
        }
        __syncthreads();
        if (t0 < NTILES) {
            #pragma unroll
            for (int i = 0; i < 8; i++) {
                int el = rowb + 8 * i;
                float4 a = x4[(size_t)sI[el] * 32 + cseg];
                float4 b = x4[(size_t)sJ[el] * 32 + cseg];
                p[i] = make_float4(a.x*b.x, a.y*b.y, a.z*b.z, a.w*b.w);
            }
        }
    } else {
        if (t0 < NTILES) {
            #pragma unroll
            for (int i = 0; i < 8; i++)
                p[i] = *(const float4*)&g_h[(size_t)(t0 * TILE + rowb + 8 * i) * C + cseg * 4];
        }
    }

    for (int t = t0; t < NTILES; t += gridDim.x) {
        const int e0 = t * TILE;
        const int tn = t + gridDim.x;
        const int nbuf = buf ^ 1;

        // ---- write A tile (hi/lo bf16) from prefetched regs ----
        #pragma unroll
        for (int i = 0; i < 8; i++) {
            float4 v = p[i];
            if (PASS == 2) {
                v.x = fmaxf(fmaf(v.x, sc4.x, sh4.x), 0.f);
                v.y = fmaxf(fmaf(v.y, sc4.y, sh4.y), 0.f);
                v.z = fmaxf(fmaf(v.z, sc4.z, sh4.z), 0.f);
                v.w = fmaxf(fmaf(v.w, sc4.w, sh4.w), 0.f);
            }
            __nv_bfloat16 h0,h1,h2,h3,l0,l1,l2,l3;
            split_bf16(v.x,h0,l0); split_bf16(v.y,h1,l1);
            split_bf16(v.z,h2,l2); split_bf16(v.w,h3,l3);
            uint32_t off = (uint32_t)((rowb + 8*i) * PITCHB + cseg * 8);
            *(uint2*)(sm + SM_AH + off) = make_uint2(pack_bf(h0,h1), pack_bf(h2,h3));
            *(uint2*)(sm + SM_AL + off) = make_uint2(pack_bf(l0,l1), pack_bf(l2,l3));
        }
        // ---- stage next tile's edge indices (pass 1) ----
        if (PASS == 1 && tn < NTILES && tid < TILE) {
            int e = tn * TILE + tid;
            if (is64) { sI[nbuf*64+tid] = (int)e64[e]; sJ[nbuf*64+tid] = (int)e64[(size_t)E_EDGES + e]; }
            else      { sI[nbuf*64+tid] = e32[e];      sJ[nbuf*64+tid] = e32[(size_t)E_EDGES + e]; }
        }
        __syncthreads();

        // ---- prefetch next tile's A data (overlaps with MMA below) ----
        if (tn < NTILES) {
            if (PASS == 1) {
                #pragma unroll
                for (int i = 0; i < 8; i++) {
                    int el = rowb + 8 * i;
                    float4 a = x4[(size_t)sI[nbuf*64+el] * 32 + cseg];
                    float4 b = x4[(size_t)sJ[nbuf*64+el] * 32 + cseg];
                    p[i] = make_float4(a.x*b.x, a.y*b.y, a.z*b.z, a.w*b.w);
                }
            } else {
                #pragma unroll
                for (int i = 0; i < 8; i++)
                    p[i] = *(const float4*)&g_h[(size_t)(tn*TILE + rowb + 8*i) * C + cseg * 4];
            }
        }

        // ---- MMA: D = Ah*Bh + Al*Bh + Ah*Bl (32x32 warp tile) ----
        float acc[2][4][4];
        #pragma unroll
        for (int mt = 0; mt < 2; mt++)
            #pragma unroll
            for (int q = 0; q < 4; q++)
                #pragma unroll
                for (int r = 0; r < 4; r++) acc[mt][q][r] = 0.f;

        #pragma unroll
        for (int ks = 0; ks < 8; ks++) {
            uint32_t ah[2][4], al[2][4];
            #pragma unroll
            for (int mb = 0; mb < 2; mb++) {
                uint32_t off = (uint32_t)((m0 + mb*16 + (lid & 15)) * PITCHB
                                          + (ks*16 + (lid >> 4) * 8) * 2);
                ldsm4(ah[mb], sb + SM_AH + off);
                ldsm4(al[mb], sb + SM_AL + off);
            }
            #pragma unroll
            for (int nb2 = 0; nb2 < 2; nb2++) {
                uint32_t boff = (uint32_t)(
                    (ks*16 + (lid & 7) + ((lid >> 3) & 1) * 8) * PITCHB
                    + (n0 + nb2*16 + (lid >> 4) * 8) * 2);
                uint32_t bh[4], bl[4];
                ldsm4t(bh, sb + SM_BH + boff);
                ldsm4t(bl, sb + SM_BL + boff);
                // dependency-spaced: same acc revisited at distance 4
                mma16816(acc[0][2*nb2],   ah[0], bh);
                mma16816(acc[1][2*nb2],   ah[1], bh);
                mma16816(acc[0][2*nb2+1], ah[0], bh+2);
                mma16816(acc[1][2*nb2+1], ah[1], bh+2);
                mma16816(acc[0][2*nb2],   al[0], bh);
                mma16816(acc[1][2*nb2],   al[1], bh);
                mma16816(acc[0][2*nb2+1], al[0], bh+2);
                mma16816(acc[1][2*nb2+1], al[1], bh+2);
                mma16816(acc[0][2*nb2],   ah[0], bl);
                mma16816(acc[1][2*nb2],   ah[1], bl);
                mma16816(acc[0][2*nb2+1], ah[0], bl+2);
                mma16816(acc[1][2*nb2+1], ah[1], bl+2);
            }
        }

        // ---- epilogue: +bias, direct STG to scratch, register stats ----
        #pragma unroll
        for (int q = 0; q < 4; q++) {
            int c0 = n0 + (q >> 1) * 16 + (q & 1) * 8 + 2 * tig;
            float2 bb = *(const float2*)&sBias[c0];
            #pragma unroll
            for (int mt = 0; mt < 2; mt++) {
                int r = m0 + mt * 16 + gid;
                float2 v0 = make_float2(acc[mt][q][0] + bb.x, acc[mt][q][1] + bb.y);
                float2 v1 = make_float2(acc[mt][q][2] + bb.x, acc[mt][q][3] + bb.y);
                *(float2*)&g_h[(size_t)(e0 + r) * C + c0]     = v0;
                *(float2*)&g_h[(size_t)(e0 + r + 8) * C + c0] = v1;
                s1v[q].x += v0.x + v1.x;          s1v[q].y += v0.y + v1.y;
                s2v[q].x += v0.x*v0.x + v1.x*v1.x; s2v[q].y += v0.y*v0.y + v1.y*v1.y;
            }
        }
        __syncthreads();   // all ldsm of this A tile done before next overwrite
        buf ^= 1;
    }

    // ---- stats: reduce over gid (xor-shuffles), then shared, then global ----
    #pragma unroll
    for (int q = 0; q < 4; q++) {
        #pragma unroll
        for (int msk = 4; msk <= 16; msk <<= 1) {
            s1v[q].x += __shfl_xor_sync(0xffffffffu, s1v[q].x, msk);
            s1v[q].y += __shfl_xor_sync(0xffffffffu, s1v[q].y, msk);
            s2v[q].x += __shfl_xor_sync(0xffffffffu, s2v[q].x, msk);
            s2v[q].y += __shfl_xor_sync(0xffffffffu, s2v[q].y, msk);
        }
    }
    if (gid == 0) {
        #pragma unroll
        for (int q = 0; q < 4; q++) {
            int c0 = n0 + (q >> 1) * 16 + (q & 1) * 8 + 2 * tig;
            atomicAdd(&sRed1[c0], s1v[q].x);  atomicAdd(&sRed1[c0+1], s1v[q].y);
            atomicAdd(&sRed2[c0], s2v[q].x);  atomicAdd(&sRed2[c0+1], s2v[q].y);
        }
    }
    __syncthreads();
    if (tid < C) {
        atomicAdd((PASS == 1 ? g_sum1 : g_sum2) + tid, sRed1[tid]);
        atomicAdd((PASS == 1 ? g_sq1 : g_sq2) + tid, sRed2[tid]);
    }
}

__global__ void k_fin(const float* __restrict__ g, const float* __restrict__ be, int which) {
    int c = threadIdx.x;
    float sum = which ? g_sum2[c] : g_sum1[c];
    float sq  = which ? g_sq2[c]  : g_sq1[c];
    float mean = sum * (1.f / E_EDGES);
    float var  = sq * (1.f / E_EDGES) - mean * mean;
    float a = g[c] * rsqrtf(var + BN_EPS);
    float cc = be[c] - mean * a;
    if (which) { g_a2[c] = a; g_c2[c] = cc; }
    else       { g_a1[c] = a; g_c1[c] = cc; }
}

__global__ __launch_bounds__(256) void k_out(const float* __restrict__ wc,
                                             const float* __restrict__ bc,
                                             float* __restrict__ out)
{
    const int lane = threadIdx.x & 31;
    const int warp = threadIdx.x >> 5;
    const int nwarp = gridDim.x * 8;
    const int wg = blockIdx.x * 8 + warp;

    float4 a2 = *(const float4*)&g_a2[lane * 4];
    float4 c2 = *(const float4*)&g_c2[lane * 4];
    float4 wv = *(const float4*)&wc[lane * 4];
    float b = bc[0];

    for (size_t e = wg; e < E_EDGES; e += nwarp) {
        float4 v = *(const float4*)&g_h[e * C + lane * 4];
        float r = fmaxf(fmaf(v.x, a2.x, c2.x), 0.f) * wv.x
                + fmaxf(fmaf(v.y, a2.y, c2.y), 0.f) * wv.y
                + fmaxf(fmaf(v.z, a2.z, c2.z), 0.f) * wv.z
                + fmaxf(fmaf(v.w, a2.w, c2.w), 0.f) * wv.w;
        #pragma unroll
        for (int s = 16; s > 0; s >>= 1) r += __shfl_xor_sync(0xffffffffu, r, s);
        if (lane == 0) out[e] = r + b;
    }
}

extern "C" void kernel_launch(void* const* d_in, const int* in_sizes, int n_in,
                              void* d_out, int out_size) {
    const float* x     = (const float*)d_in[0];
    const void*  edges = d_in[1];
    const float* w1    = (const float*)d_in[2];
    const float* b1    = (const float*)d_in[3];
    const float* g1    = (const float*)d_in[4];
    const float* be1   = (const float*)d_in[5];
    const float* w2    = (const float*)d_in[6];
    const float* b2    = (const float*)d_in[7];
    const float* g2    = (const float*)d_in[8];
    const float* be2   = (const float*)d_in[9];
    const float* wc    = (const float*)d_in[10];
    const float* bc    = (const float*)d_in[11];
    float* out = (float*)d_out;
    (void)in_sizes; (void)n_in; (void)out_size;

    cudaFuncSetAttribute(k_pass_mma<1>, cudaFuncAttributeMaxDynamicSharedMemorySize, SM_TOTAL);
    cudaFuncSetAttribute(k_pass_mma<2>, cudaFuncAttributeMaxDynamicSharedMemorySize, SM_TOTAL);

    k_zero<<<1, 128>>>((const unsigned*)edges);
    k_pass_mma<1><<<296, 256, SM_TOTAL>>>(x, edges, w1, b1);
    k_fin<<<1, 128>>>(g1, be1, 0);
    k_pass_mma<2><<<296, 256, SM_TOTAL>>>(x, edges, w2, b2);
    k_fin<<<1, 128>>>(g2, be2, 1);
    k_out<<<2048, 256>>>(wc, bc, out);
}

// round 12
// speedup vs baseline: 1.5525x; 1.0177x over previous
#include <cuda_runtime.h>
#include <cuda_bf16.h>
#include <cstdint>

#define C 128
#define E_EDGES 1000000
#define TILE 64
#define NTILES (E_EDGES / TILE)   // 15625 exact
#define BN_EPS 1e-5f
#define PITCHB 272   // bytes per bf16 A-tile row (136 halves: 128 data + 8 pad)

// ---------------- SMEM layout: A double-buffered, B lives in L2 ----------------
#define SM_ABUF(b) ((b) * 34816)   // hi at +0 (17408), lo at +17408
#define SM_ALO   17408
#define SM_BIAS  69632   // float[128]
#define SM_SCALE 70144   // float[128]
#define SM_SHIFT 70656   // float[128]
#define SM_RED1  71168   // float[128]
#define SM_RED2  71680   // float[128]
#define SM_TOTAL 72192

// 512 MB scratch for h1pre (pass1 -> pass2) then h2pre (pass2 -> out), in place.
__device__ float g_h[(size_t)E_EDGES * C];
// B in fragment-major layout: [pass][hi/lo][(ks*8 + j)*32 + lane] -> uint4 (regs b0..b3)
__device__ uint4 g_Bfrag[2][2][2048];
__device__ __align__(16) float g_sum1[C], g_sq1[C], g_sum2[C], g_sq2[C];
__device__ __align__(16) float g_a1[C], g_c1[C], g_a2[C], g_c2[C];
__device__ int g_is64;

// ---------------- helpers ----------------
typedef unsigned long long ull;
__device__ __forceinline__ uint32_t smem_u32(const void* p) {
    uint32_t a;
    asm("{ .reg .u64 t; cvta.to.shared.u64 t, %1; cvt.u32.u64 %0, t; }" : "=r"(a) : "l"(p));
    return a;
}
__device__ __forceinline__ void ldsm4(uint32_t* r, uint32_t addr) {
    asm volatile("ldmatrix.sync.aligned.m8n8.x4.shared.b16 {%0,%1,%2,%3}, [%4];"
                 : "=r"(r[0]), "=r"(r[1]), "=r"(r[2]), "=r"(r[3]) : "r"(addr));
}
__device__ __forceinline__ void mma16816(float* d, const uint32_t* a, const uint32_t* b) {
    asm volatile(
        "mma.sync.aligned.m16n8k16.row.col.f32.bf16.bf16.f32 "
        "{%0,%1,%2,%3}, {%4,%5,%6,%7}, {%8,%9}, {%0,%1,%2,%3};"
        : "+f"(d[0]), "+f"(d[1]), "+f"(d[2]), "+f"(d[3])
        : "r"(a[0]), "r"(a[1]), "r"(a[2]), "r"(a[3]), "r"(b[0]), "r"(b[1]));
}
__device__ __forceinline__ ull pk2(float x, float y) {
    ull r; asm("mov.b64 %0, {%1, %2};" : "=l"(r) : "f"(x), "f"(y)); return r;
}
__device__ __forceinline__ float2 up2(ull v) {
    float2 r; asm("mov.b64 {%0, %1}, %2;" : "=f"(r.x), "=f"(r.y) : "l"(v)); return r;
}
__device__ __forceinline__ ull add2(ull a, ull b) {
    ull r; asm("add.rn.f32x2 %0, %1, %2;" : "=l"(r) : "l"(a), "l"(b)); return r;
}
__device__ __forceinline__ ull fma2(ull a, ull b, ull c) {
    ull r; asm("fma.rn.f32x2 %0, %1, %2, %3;" : "=l"(r) : "l"(a), "l"(b), "l"(c)); return r;
}
__device__ __forceinline__ void split_bf16(float v, __nv_bfloat16& h, __nv_bfloat16& l) {
    h = __float2bfloat16_rn(v);
    l = __float2bfloat16_rn(v - __bfloat162float(h));
}
__device__ __forceinline__ uint32_t pack_bf(__nv_bfloat16 a, __nv_bfloat16 b) {
    return ((uint32_t)__bfloat16_as_ushort(b) << 16) | __bfloat16_as_ushort(a);
}

// ---- prep: zero stats, sniff edge dtype, pack W1/W2 into fragment-major hi/lo ----
__global__ void k_prep(const unsigned* __restrict__ ew,
                       const float* __restrict__ w1, const float* __restrict__ w2) {
    int t = blockIdx.x * 256 + threadIdx.x;       // 0..4095
    if (t < C) { g_sum1[t] = 0.f; g_sq1[t] = 0.f; g_sum2[t] = 0.f; g_sq2[t] = 0.f; }
    if (t == 0) {
        // int64 edge data (non-negative < 2^31) has every odd 32-bit word == 0
        int all0 = 1;
        #pragma unroll
        for (int k = 0; k < 8; k++) all0 &= (ew[2 * k + 1] == 0u);
        g_is64 = all0;
    }
    int p   = t >> 11;            // which weight matrix
    int idx = t & 2047;
    const float* w = p ? w2 : w1;
    int ks = idx >> 8, j = (idx >> 5) & 7, lid = idx & 31;
    int q = lid & 3, nn = lid >> 2;
    uint32_t hi[4], lo[4];
    #pragma unroll
    for (int r = 0; r < 4; r++) {
        int k = ks * 16 + 2 * q + (r & 1) * 8;
        int n = j * 16 + nn + (r >> 1) * 8;
        float v0 = w[k * C + n], v1 = w[(k + 1) * C + n];
        __nv_bfloat16 h0, l0, h1, l1;
        split_bf16(v0, h0, l0); split_bf16(v1, h1, l1);
        hi[r] = pack_bf(h0, h1);     // element with smaller k in low 16 bits
        lo[r] = pack_bf(l0, l1);
    }
    g_Bfrag[p][0][idx] = make_uint4(hi[0], hi[1], hi[2], hi[3]);
    g_Bfrag[p][1][idx] = make_uint4(lo[0], lo[1], lo[2], lo[3]);
}

// PASS 1: A = x[i]*x[j] (gather), B = w1, D -> h1pre -> g_h, stats1
// PASS 2: A = relu(a1*g_h + c1),  B = w2, D -> h2pre -> g_h, stats2
template <int PASS>
__global__ __launch_bounds__(256, 2) void k_pass_mma(
    const float* __restrict__ x, const void* __restrict__ edges_raw,
    const float* __restrict__ bias)
{
    extern __shared__ char sm[];
    const uint32_t sb = smem_u32(sm);
    const int tid = threadIdx.x;
    const int wid = tid >> 5;
    const int lid = tid & 31;
    const int gid = lid >> 2;
    const int tig = lid & 3;
    const int m0 = (wid & 1) * 32;    // warp's 32 rows
    const int n0 = (wid >> 1) * 32;   // warp's 32 cols
    const int jb = (wid >> 1) * 2;    // B n16-chunk base

    float* sBias  = (float*)(sm + SM_BIAS);
    float* sScale = (float*)(sm + SM_SCALE);
    float* sShift = (float*)(sm + SM_SHIFT);
    float* sRed1  = (float*)(sm + SM_RED1);
    float* sRed2  = (float*)(sm + SM_RED2);

    if (tid < C) {
        sBias[tid] = bias[tid];
        sRed1[tid] = 0.f; sRed2[tid] = 0.f;
        if (PASS == 2) { sScale[tid] = g_a1[tid]; sShift[tid] = g_c1[tid]; }
    }
    __syncthreads();

    const int is64 = g_is64;
    const long long* e64 = (const long long*)edges_raw;
    const int*       e32 = (const int*)edges_raw;
    const float4*    x4  = (const float4*)x;
    const uint4* __restrict__ Bh = &g_Bfrag[PASS - 1][0][0];
    const uint4* __restrict__ Bl = &g_Bfrag[PASS - 1][1][0];

    const int rowb = wid;         // prefetch rows rowb + 8i (warp-uniform)
    const int cseg = lid;         // float4 column group

    float4 sc4 = make_float4(0.f,0.f,0.f,0.f), sh4 = sc4;
    if (PASS == 2) {
        sc4 = *(const float4*)&sScale[cseg * 4];
        sh4 = *(const float4*)&sShift[cseg * 4];
    }

    ull s1v[4], s2v[4];
    #pragma unroll
    for (int q = 0; q < 4; q++) { s1v[q] = 0ull; s2v[q] = 0ull; }

    float4 p[8];

    #define PREFETCH(tt)                                                            \
        _Pragma("unroll")                                                           \
        for (int i = 0; i < 8; i++) {                                               \
            int e = (tt) * TILE + rowb + 8 * i;                                     \
            if (PASS == 1) {                                                        \
                int ei, ej;                                                         \
                if (is64) { ei = (int)e64[e]; ej = (int)e64[(size_t)E_EDGES + e]; } \
                else      { ei = e32[e];      ej = e32[(size_t)E_EDGES + e]; }      \
                float4 a = x4[(size_t)ei * 32 + cseg];                              \
                float4 b = x4[(size_t)ej * 32 + cseg];                              \
                p[i] = make_float4(a.x*b.x, a.y*b.y, a.z*b.z, a.w*b.w);             \
            } else {                                                                \
                p[i] = *(const float4*)&g_h[(size_t)e * C + cseg * 4];              \
            }                                                                       \
        }

    #define STORE_A(bufbase)                                                        \
        _Pragma("unroll")                                                           \
        for (int i = 0; i < 8; i++) {                                               \
            float4 v = p[i];                                                        \
            if (PASS == 2) {                                                        \
                v.x = fmaxf(fmaf(v.x, sc4.x, sh4.x), 0.f);                          \
                v.y = fmaxf(fmaf(v.y, sc4.y, sh4.y), 0.f);                          \
                v.z = fmaxf(fmaf(v.z, sc4.z, sh4.z), 0.f);                          \
                v.w = fmaxf(fmaf(v.w, sc4.w, sh4.w), 0.f);                          \
            }                                                                       \
            __nv_bfloat16 h0,h1,h2,h3,l0,l1,l2,l3;                                  \
            split_bf16(v.x,h0,l0); split_bf16(v.y,h1,l1);                           \
            split_bf16(v.z,h2,l2); split_bf16(v.w,h3,l3);                           \
            uint32_t off = (uint32_t)((rowb + 8*i) * PITCHB + cseg * 8);            \
            *(uint2*)(sm + (bufbase) + off) = make_uint2(pack_bf(h0,h1), pack_bf(h2,h3)); \
            *(uint2*)(sm + (bufbase) + SM_ALO + off) = make_uint2(pack_bf(l0,l1), pack_bf(l2,l3)); \
        }

    // ---- prologue: fill buffer 0 with tile t0 ----
    const int t0 = blockIdx.x;
    PREFETCH(t0);
    STORE_A(SM_ABUF(0));
    __syncthreads();

    int cur = 0;
    for (int t = t0; t < NTILES; t += gridDim.x) {
        const int e0 = t * TILE;
        const int tn = t + gridDim.x;

        // ---- prefetch next tile into registers (overlaps MMA) ----
        if (tn < NTILES) { PREFETCH(tn); }

        // ---- MMA: D = Ah*Bh + Al*Bh + Ah*Bl; A from smem, B from L2 ----
        const uint32_t aH = sb + SM_ABUF(cur);
        const uint32_t aL = aH + SM_ALO;

        float acc[2][4][4];
        #pragma unroll
        for (int mt = 0; mt < 2; mt++)
            #pragma unroll
            for (int q = 0; q < 4; q++)
                #pragma unroll
                for (int r = 0; r < 4; r++) acc[mt][q][r] = 0.f;

        #pragma unroll
        for (int ks = 0; ks < 8; ks++) {
            uint32_t ah[2][4], al[2][4];
            #pragma unroll
            for (int mb = 0; mb < 2; mb++) {
                uint32_t off = (uint32_t)((m0 + mb*16 + (lid & 15)) * PITCHB
                                          + (ks*16 + (lid >> 4) * 8) * 2);
                ldsm4(ah[mb], aH + off);
                ldsm4(al[mb], aL + off);
            }
            #pragma unroll
            for (int nb2 = 0; nb2 < 2; nb2++) {
                uint4 bhv = Bh[(ks * 8 + jb + nb2) * 32 + lid];
                uint4 blv = Bl[(ks * 8 + jb + nb2) * 32 + lid];
                const uint32_t* bh = (const uint32_t*)&bhv;
                const uint32_t* bl = (const uint32_t*)&blv;
                mma16816(acc[0][2*nb2],   ah[0], bh);
                mma16816(acc[1][2*nb2],   ah[1], bh);
                mma16816(acc[0][2*nb2+1], ah[0], bh+2);
                mma16816(acc[1][2*nb2+1], ah[1], bh+2);
                mma16816(acc[0][2*nb2],   al[0], bh);
                mma16816(acc[1][2*nb2],   al[1], bh);
                mma16816(acc[0][2*nb2+1], al[0], bh+2);
                mma16816(acc[1][2*nb2+1], al[1], bh+2);
                mma16816(acc[0][2*nb2],   ah[0], bl);
                mma16816(acc[1][2*nb2],   ah[1], bl);
                mma16816(acc[0][2*nb2+1], ah[0], bl+2);
                mma16816(acc[1][2*nb2+1], ah[1], bl+2);
            }
        }

        // ---- epilogue: +bias (f32x2), direct STG, packed stats ----
        #pragma unroll
        for (int q = 0; q < 4; q++) {
            int c0 = n0 + (q >> 1) * 16 + (q & 1) * 8 + 2 * tig;
            ull bb = *(const ull*)&sBias[c0];
            #pragma unroll
            for (int mt = 0; mt < 2; mt++) {
                int r = m0 + mt * 16 + gid;
                ull v0 = add2(pk2(acc[mt][q][0], acc[mt][q][1]), bb);
                ull v1 = add2(pk2(acc[mt][q][2], acc[mt][q][3]), bb);
                *(ull*)&g_h[(size_t)(e0 + r) * C + c0]     = v0;
                *(ull*)&g_h[(size_t)(e0 + r + 8) * C + c0] = v1;
                s1v[q] = add2(s1v[q], v0);  s1v[q] = add2(s1v[q], v1);
                s2v[q] = fma2(v0, v0, s2v[q]);  s2v[q] = fma2(v1, v1, s2v[q]);
            }
        }

        // ---- write next tile's A into the other buffer, single barrier ----
        if (tn < NTILES) { STORE_A(SM_ABUF(cur ^ 1)); }
        __syncthreads();
        cur ^= 1;
    }

    // ---- stats: reduce over gid (xor-shuffles), then shared, then global ----
    #pragma unroll
    for (int q = 0; q < 4; q++) {
        float2 a = up2(s1v[q]), b = up2(s2v[q]);
        #pragma unroll
        for (int msk = 4; msk <= 16; msk <<= 1) {
            a.x += __shfl_xor_sync(0xffffffffu, a.x, msk);
            a.y += __shfl_xor_sync(0xffffffffu, a.y, msk);
            b.x += __shfl_xor_sync(0xffffffffu, b.x, msk);
            b.y += __shfl_xor_sync(0xffffffffu, b.y, msk);
        }
        if (gid == 0) {
            int c0 = n0 + (q >> 1) * 16 + (q & 1) * 8 + 2 * tig;
            atomicAdd(&sRed1[c0], a.x);  atomicAdd(&sRed1[c0+1], a.y);
            atomicAdd(&sRed2[c0], b.x);  atomicAdd(&sRed2[c0+1], b.y);
        }
    }
    __syncthreads();
    if (tid < C) {
        atomicAdd((PASS == 1 ? g_sum1 : g_sum2) + tid, sRed1[tid]);
        atomicAdd((PASS == 1 ? g_sq1 : g_sq2) + tid, sRed2[tid]);
    }
}

__global__ void k_fin(const float* __restrict__ g, const float* __restrict__ be, int which) {
    int c = threadIdx.x;
    float sum = which ? g_sum2[c] : g_sum1[c];
    float sq  = which ? g_sq2[c]  : g_sq1[c];
    float mean = sum * (1.f / E_EDGES);
    float var  = sq * (1.f / E_EDGES) - mean * mean;
    float a = g[c] * rsqrtf(var + BN_EPS);
    float cc = be[c] - mean * a;
    if (which) { g_a2[c] = a; g_c2[c] = cc; }
    else       { g_a1[c] = a; g_c1[c] = cc; }
}

__global__ __launch_bounds__(256) void k_out(const float* __restrict__ wc,
                                             const float* __restrict__ bc,
                                             float* __restrict__ out)
{
    const int lane = threadIdx.x & 31;
    const int warp = threadIdx.x >> 5;
    const int nwarp = gridDim.x * 8;
    const int wg = blockIdx.x * 8 + warp;

    float4 a2 = *(const float4*)&g_a2[lane * 4];
    float4 c2 = *(const float4*)&g_c2[lane * 4];
    float4 wv = *(const float4*)&wc[lane * 4];
    float b = bc[0];

    for (size_t e = wg; e < E_EDGES; e += nwarp) {
        float4 v = *(const float4*)&g_h[e * C + lane * 4];
        float r = fmaxf(fmaf(v.x, a2.x, c2.x), 0.f) * wv.x
                + fmaxf(fmaf(v.y, a2.y, c2.y), 0.f) * wv.y
                + fmaxf(fmaf(v.z, a2.z, c2.z), 0.f) * wv.z
                + fmaxf(fmaf(v.w, a2.w, c2.w), 0.f) * wv.w;
        #pragma unroll
        for (int s = 16; s > 0; s >>= 1) r += __shfl_xor_sync(0xffffffffu, r, s);
        if (lane == 0) out[e] = r + b;
    }
}

extern "C" void kernel_launch(void* const* d_in, const int* in_sizes, int n_in,
                              void* d_out, int out_size) {
    const float* x     = (const float*)d_in[0];
    const void*  edges = d_in[1];
    const float* w1    = (const float*)d_in[2];
    const float* b1    = (const float*)d_in[3];
    const float* g1    = (const float*)d_in[4];
    const float* be1   = (const float*)d_in[5];
    const float* w2    = (const float*)d_in[6];
    const float* b2    = (const float*)d_in[7];
    const float* g2    = (const float*)d_in[8];
    const float* be2   = (const float*)d_in[9];
    const float* wc    = (const float*)d_in[10];
    const float* bc    = (const float*)d_in[11];
    float* out = (float*)d_out;
    (void)in_sizes; (void)n_in; (void)out_size;

    cudaFuncSetAttribute(k_pass_mma<1>, cudaFuncAttributeMaxDynamicSharedMemorySize, SM_TOTAL);
    cudaFuncSetAttribute(k_pass_mma<2>, cudaFuncAttributeMaxDynamicSharedMemorySize, SM_TOTAL);

    k_prep<<<16, 256>>>((const unsigned*)edges, w1, w2);
    k_pass_mma<1><<<296, 256, SM_TOTAL>>>(x, edges, b1);
    k_fin<<<1, 128>>>(g1, be1, 0);
    k_pass_mma<2><<<296, 256, SM_TOTAL>>>(x, edges, b2);
    k_fin<<<1, 128>>>(g2, be2, 1);
    k_out<<<2048, 256>>>(wc, bc, out);
}

// round 13
// speedup vs baseline: 2.2552x; 1.4526x over previous
#include <cuda_runtime.h>
#include <cuda_fp16.h>
#include <cstdint>

#define C 128
#define E_EDGES 1000000
#define TILE 64
#define NTILES (E_EDGES / TILE)   // 15625 exact
#define BN_EPS 1e-5f
#define PITCHB 272   // bytes per fp16 A-tile row (136 halves: 128 data + 8 pad)

// ---------------- SMEM layout: A (fp16, single-plane) double-buffered ----------------
#define SM_ABUF(b) ((b) * 17408)
#define SM_BIAS  34816   // float[128]
#define SM_SCALE 35328   // float[128]
#define SM_SHIFT 35840   // float[128]
#define SM_RED1  36352   // float[128]
#define SM_RED2  36864   // float[128]
#define SM_TOTAL 37376

// 512 MB scratch for h1pre (pass1 -> pass2) then h2pre (pass2 -> out), in place.
__device__ float g_h[(size_t)E_EDGES * C];
// B in fragment-major fp16 layout: [pass][(ks*8 + j)*32 + lane] -> uint4 (regs b0..b3)
__device__ uint4 g_Bfrag[2][2048];
__device__ __align__(16) float g_sum1[C], g_sq1[C], g_sum2[C], g_sq2[C];
__device__ __align__(16) float g_a1[C], g_c1[C], g_a2[C], g_c2[C];
__device__ int g_is64;

// ---------------- helpers ----------------
typedef unsigned long long ull;
__device__ __forceinline__ uint32_t smem_u32(const void* p) {
    uint32_t a;
    asm("{ .reg .u64 t; cvta.to.shared.u64 t, %1; cvt.u32.u64 %0, t; }" : "=r"(a) : "l"(p));
    return a;
}
__device__ __forceinline__ void ldsm4(uint32_t* r, uint32_t addr) {
    asm volatile("ldmatrix.sync.aligned.m8n8.x4.shared.b16 {%0,%1,%2,%3}, [%4];"
                 : "=r"(r[0]), "=r"(r[1]), "=r"(r[2]), "=r"(r[3]) : "r"(addr));
}
__device__ __forceinline__ void mma16816h(float* d, const uint32_t* a, const uint32_t* b) {
    asm volatile(
        "mma.sync.aligned.m16n8k16.row.col.f32.f16.f16.f32 "
        "{%0,%1,%2,%3}, {%4,%5,%6,%7}, {%8,%9}, {%0,%1,%2,%3};"
        : "+f"(d[0]), "+f"(d[1]), "+f"(d[2]), "+f"(d[3])
        : "r"(a[0]), "r"(a[1]), "r"(a[2]), "r"(a[3]), "r"(b[0]), "r"(b[1]));
}
__device__ __forceinline__ ull pk2(float x, float y) {
    ull r; asm("mov.b64 %0, {%1, %2};" : "=l"(r) : "f"(x), "f"(y)); return r;
}
__device__ __forceinline__ float2 up2(ull v) {
    float2 r; asm("mov.b64 {%0, %1}, %2;" : "=f"(r.x), "=f"(r.y) : "l"(v)); return r;
}
__device__ __forceinline__ ull add2(ull a, ull b) {
    ull r; asm("add.rn.f32x2 %0, %1, %2;" : "=l"(r) : "l"(a), "l"(b)); return r;
}
__device__ __forceinline__ ull fma2(ull a, ull b, ull c) {
    ull r; asm("fma.rn.f32x2 %0, %1, %2, %3;" : "=l"(r) : "l"(a), "l"(b), "l"(c)); return r;
}
__device__ __forceinline__ uint32_t pack_h2(float a, float b) {
    __half2 h = __floats2half2_rn(a, b);
    return *(uint32_t*)&h;
}

// ---- prep: zero stats, sniff edge dtype, pack W1/W2 into fragment-major fp16 ----
__global__ void k_prep(const unsigned* __restrict__ ew,
                       const float* __restrict__ w1, const float* __restrict__ w2) {
    int t = blockIdx.x * 256 + threadIdx.x;       // 0..4095
    if (t < C) { g_sum1[t] = 0.f; g_sq1[t] = 0.f; g_sum2[t] = 0.f; g_sq2[t] = 0.f; }
    if (t == 0) {
        // int64 edge data (non-negative < 2^31) has every odd 32-bit word == 0
        int all0 = 1;
        #pragma unroll
        for (int k = 0; k < 8; k++) all0 &= (ew[2 * k + 1] == 0u);
        g_is64 = all0;
    }
    int p   = t >> 11;            // which weight matrix
    int idx = t & 2047;
    const float* w = p ? w2 : w1;
    int ks = idx >> 8, j = (idx >> 5) & 7, lid = idx & 31;
    int q = lid & 3, nn = lid >> 2;
    uint32_t fr[4];
    #pragma unroll
    for (int r = 0; r < 4; r++) {
        int k = ks * 16 + 2 * q + (r & 1) * 8;
        int n = j * 16 + nn + (r >> 1) * 8;
        fr[r] = pack_h2(w[k * C + n], w[(k + 1) * C + n]);  // smaller k in low 16 bits
    }
    g_Bfrag[p][idx] = make_uint4(fr[0], fr[1], fr[2], fr[3]);
}

// PASS 1: A = x[i]*x[j] (gather), B = w1, D -> h1pre -> g_h, stats1
// PASS 2: A = relu(a1*g_h + c1),  B = w2, D -> h2pre -> g_h, stats2
template <int PASS>
__global__ __launch_bounds__(256, 2) void k_pass_mma(
    const float* __restrict__ x, const void* __restrict__ edges_raw,
    const float* __restrict__ bias)
{
    extern __shared__ char sm[];
    const uint32_t sb = smem_u32(sm);
    const int tid = threadIdx.x;
    const int wid = tid >> 5;
    const int lid = tid & 31;
    const int gid = lid >> 2;
    const int tig = lid & 3;
    const int m0 = (wid & 1) * 32;    // warp's 32 rows
    const int n0 = (wid >> 1) * 32;   // warp's 32 cols
    const int jb = (wid >> 1) * 2;    // B n16-chunk base

    float* sBias  = (float*)(sm + SM_BIAS);
    float* sScale = (float*)(sm + SM_SCALE);
    float* sShift = (float*)(sm + SM_SHIFT);
    float* sRed1  = (float*)(sm + SM_RED1);
    float* sRed2  = (float*)(sm + SM_RED2);

    if (tid < C) {
        sBias[tid] = bias[tid];
        sRed1[tid] = 0.f; sRed2[tid] = 0.f;
        if (PASS == 2) { sScale[tid] = g_a1[tid]; sShift[tid] = g_c1[tid]; }
    }
    __syncthreads();

    const int is64 = g_is64;
    const long long* e64 = (const long long*)edges_raw;
    const int*       e32 = (const int*)edges_raw;
    const float4*    x4  = (const float4*)x;
    const uint4* __restrict__ Bf = &g_Bfrag[PASS - 1][0];

    const int rowb = wid;         // prefetch rows rowb + 8i (warp-uniform)
    const int cseg = lid;         // float4 column group

    float4 sc4 = make_float4(0.f,0.f,0.f,0.f), sh4 = sc4;
    if (PASS == 2) {
        sc4 = *(const float4*)&sScale[cseg * 4];
        sh4 = *(const float4*)&sShift[cseg * 4];
    }

    ull s1v[4], s2v[4];
    #pragma unroll
    for (int q = 0; q < 4; q++) { s1v[q] = 0ull; s2v[q] = 0ull; }

    float4 p[8];

    #define PREFETCH(tt)                                                            \
        _Pragma("unroll")                                                           \
        for (int i = 0; i < 8; i++) {                                               \
            int e = (tt) * TILE + rowb + 8 * i;                                     \
            if (PASS == 1) {                                                        \
                int ei, ej;                                                         \
                if (is64) { ei = (int)e64[e]; ej = (int)e64[(size_t)E_EDGES + e]; } \
                else      { ei = e32[e];      ej = e32[(size_t)E_EDGES + e]; }      \
                float4 a = x4[(size_t)ei * 32 + cseg];                              \
                float4 b = x4[(size_t)ej * 32 + cseg];                              \
                p[i] = make_float4(a.x*b.x, a.y*b.y, a.z*b.z, a.w*b.w);             \
            } else {                                                                \
                p[i] = *(const float4*)&g_h[(size_t)e * C + cseg * 4];              \
            }                                                                       \
        }

    #define STORE_A(bufbase)                                                        \
        _Pragma("unroll")                                                           \
        for (int i = 0; i < 8; i++) {                                               \
            float4 v = p[i];                                                        \
            if (PASS == 2) {                                                        \
                v.x = fmaxf(fmaf(v.x, sc4.x, sh4.x), 0.f);                          \
                v.y = fmaxf(fmaf(v.y, sc4.y, sh4.y), 0.f);                          \
                v.z = fmaxf(fmaf(v.z, sc4.z, sh4.z), 0.f);                          \
                v.w = fmaxf(fmaf(v.w, sc4.w, sh4.w), 0.f);                          \
            }                                                                       \
            uint32_t u0 = pack_h2(v.x, v.y);                                        \
            uint32_t u1 = pack_h2(v.z, v.w);                                        \
            uint32_t off = (uint32_t)((rowb + 8*i) * PITCHB + cseg * 8);            \
            *(uint2*)(sm + (bufbase) + off) = make_uint2(u0, u1);                   \
        }

    // ---- prologue: fill buffer 0 with tile t0 ----
    const int t0 = blockIdx.x;
    PREFETCH(t0);
    STORE_A(SM_ABUF(0));
    __syncthreads();

    int cur = 0;
    for (int t = t0; t < NTILES; t += gridDim.x) {
        const int e0 = t * TILE;
        const int tn = t + gridDim.x;

        // ---- prefetch next tile into registers (overlaps MMA) ----
        if (tn < NTILES) { PREFETCH(tn); }

        // ---- MMA: D = A*B (single fp16 term); A from smem, B from L2 ----
        const uint32_t aB = sb + SM_ABUF(cur);

        float acc[2][4][4];
        #pragma unroll
        for (int mt = 0; mt < 2; mt++)
            #pragma unroll
            for (int q = 0; q < 4; q++)
                #pragma unroll
                for (int r = 0; r < 4; r++) acc[mt][q][r] = 0.f;

        #pragma unroll
        for (int ks = 0; ks < 8; ks++) {
            uint32_t ah[2][4];
            #pragma unroll
            for (int mb = 0; mb < 2; mb++) {
                uint32_t off = (uint32_t)((m0 + mb*16 + (lid & 15)) * PITCHB
                                          + (ks*16 + (lid >> 4) * 8) * 2);
                ldsm4(ah[mb], aB + off);
            }
            #pragma unroll
            for (int nb2 = 0; nb2 < 2; nb2++) {
                uint4 bv = Bf[(ks * 8 + jb + nb2) * 32 + lid];
                const uint32_t* b = (const uint32_t*)&bv;
                mma16816h(acc[0][2*nb2],   ah[0], b);
                mma16816h(acc[1][2*nb2],   ah[1], b);
                mma16816h(acc[0][2*nb2+1], ah[0], b+2);
                mma16816h(acc[1][2*nb2+1], ah[1], b+2);
            }
        }

        // ---- epilogue: +bias (f32x2), direct STG, packed stats ----
        #pragma unroll
        for (int q = 0; q < 4; q++) {
            int c0 = n0 + (q >> 1) * 16 + (q & 1) * 8 + 2 * tig;
            ull bb = *(const ull*)&sBias[c0];
            #pragma unroll
            for (int mt = 0; mt < 2; mt++) {
                int r = m0 + mt * 16 + gid;
                ull v0 = add2(pk2(acc[mt][q][0], acc[mt][q][1]), bb);
                ull v1 = add2(pk2(acc[mt][q][2], acc[mt][q][3]), bb);
                *(ull*)&g_h[(size_t)(e0 + r) * C + c0]     = v0;
                *(ull*)&g_h[(size_t)(e0 + r + 8) * C + c0] = v1;
                s1v[q] = add2(s1v[q], v0);  s1v[q] = add2(s1v[q], v1);
                s2v[q] = fma2(v0, v0, s2v[q]);  s2v[q] = fma2(v1, v1, s2v[q]);
            }
        }

        // ---- write next tile's A into the other buffer, single barrier ----
        if (tn < NTILES) { STORE_A(SM_ABUF(cur ^ 1)); }
        __syncthreads();
        cur ^= 1;
    }

    // ---- stats: reduce over gid (xor-shuffles), then shared, then global ----
    #pragma unroll
    for (int q = 0; q < 4; q++) {
        float2 a = up2(s1v[q]), b = up2(s2v[q]);
        #pragma unroll
        for (int msk = 4; msk <= 16; msk <<= 1) {
            a.x += __shfl_xor_sync(0xffffffffu, a.x, msk);
            a.y += __shfl_xor_sync(0xffffffffu, a.y, msk);
            b.x += __shfl_xor_sync(0xffffffffu, b.x, msk);
            b.y += __shfl_xor_sync(0xffffffffu, b.y, msk);
        }
        if (gid == 0) {
            int c0 = n0 + (q >> 1) * 16 + (q & 1) * 8 + 2 * tig;
            atomicAdd(&sRed1[c0], a.x);  atomicAdd(&sRed1[c0+1], a.y);
            atomicAdd(&sRed2[c0], b.x);  atomicAdd(&sRed2[c0+1], b.y);
        }
    }
    __syncthreads();
    if (tid < C) {
        atomicAdd((PASS == 1 ? g_sum1 : g_sum2) + tid, sRed1[tid]);
        atomicAdd((PASS == 1 ? g_sq1 : g_sq2) + tid, sRed2[tid]);
    }
}

__global__ void k_fin(const float* __restrict__ g, const float* __restrict__ be, int which) {
    int c = threadIdx.x;
    float sum = which ? g_sum2[c] : g_sum1[c];
    float sq  = which ? g_sq2[c]  : g_sq1[c];
    float mean = sum * (1.f / E_EDGES);
    float var  = sq * (1.f / E_EDGES) - mean * mean;
    float a = g[c] * rsqrtf(var + BN_EPS);
    float cc = be[c] - mean * a;
    if (which) { g_a2[c] = a; g_c2[c] = cc; }
    else       { g_a1[c] = a; g_c1[c] = cc; }
}

__global__ __launch_bounds__(256) void k_out(const float* __restrict__ wc,
                                             const float* __restrict__ bc,
                                             float* __restrict__ out)
{
    const int lane = threadIdx.x & 31;
    const int warp = threadIdx.x >> 5;
    const int nwarp = gridDim.x * 8;
    const int wg = blockIdx.x * 8 + warp;

    float4 a2 = *(const float4*)&g_a2[lane * 4];
    float4 c2 = *(const float4*)&g_c2[lane * 4];
    float4 wv = *(const float4*)&wc[lane * 4];
    float b = bc[0];

    for (size_t e = wg; e < E_EDGES; e += nwarp) {
        float4 v = *(const float4*)&g_h[e * C + lane * 4];
        float r = fmaxf(fmaf(v.x, a2.x, c2.x), 0.f) * wv.x
                + fmaxf(fmaf(v.y, a2.y, c2.y), 0.f) * wv.y
                + fmaxf(fmaf(v.z, a2.z, c2.z), 0.f) * wv.z
                + fmaxf(fmaf(v.w, a2.w, c2.w), 0.f) * wv.w;
        #pragma unroll
        for (int s = 16; s > 0; s >>= 1) r += __shfl_xor_sync(0xffffffffu, r, s);
        if (lane == 0) out[e] = r + b;
    }
}

extern "C" void kernel_launch(void* const* d_in, const int* in_sizes, int n_in,
                              void* d_out, int out_size) {
    const float* x     = (const float*)d_in[0];
    const void*  edges = d_in[1];
    const float* w1    = (const float*)d_in[2];
    const float* b1    = (const float*)d_in[3];
    const float* g1    = (const float*)d_in[4];
    const float* be1   = (const float*)d_in[5];
    const float* w2    = (const float*)d_in[6];
    const float* b2    = (const float*)d_in[7];
    const float* g2    = (const float*)d_in[8];
    const float* be2   = (const float*)d_in[9];
    const float* wc    = (const float*)d_in[10];
    const float* bc    = (const float*)d_in[11];
    float* out = (float*)d_out;
    (void)in_sizes; (void)n_in; (void)out_size;

    cudaFuncSetAttribute(k_pass_mma<1>, cudaFuncAttributeMaxDynamicSharedMemorySize, SM_TOTAL);
    cudaFuncSetAttribute(k_pass_mma<2>, cudaFuncAttributeMaxDynamicSharedMemorySize, SM_TOTAL);

    k_prep<<<16, 256>>>((const unsigned*)edges, w1, w2);
    k_pass_mma<1><<<296, 256, SM_TOTAL>>>(x, edges, b1);
    k_fin<<<1, 128>>>(g1, be1, 0);
    k_pass_mma<2><<<296, 256, SM_TOTAL>>>(x, edges, b2);
    k_fin<<<1, 128>>>(g2, be2, 1);
    k_out<<<2048, 256>>>(wc, bc, out);
}

// round 14
// speedup vs baseline: 2.5119x; 1.1138x over previous
#include <cuda_runtime.h>
#include <cuda_fp16.h>
#include <cstdint>

#define C 128
#define E_EDGES 1000000
#define TILE 64
#define NTILES (E_EDGES / TILE)   // 15625 exact
#define BN_EPS 1e-5f
#define PITCHB 272   // bytes per fp16 A-tile row (136 halves: 128 data + 8 pad)

// ---------------- SMEM layout: A (fp16, single-plane) double-buffered ----------------
#define SM_ABUF(b) ((b) * 17408)
#define SM_BIAS  34816   // float[128]
#define SM_SCALE 35328   // float[128]
#define SM_SHIFT 35840   // float[128]
#define SM_RED1  36352   // float[128]
#define SM_RED2  36864   // float[128]
#define SM_TOTAL 37376

// 256 MB fp16 scratch for h1pre (pass1 -> pass2) then h2pre (pass2 -> out), in place.
__device__ __half g_h[(size_t)E_EDGES * C];
// B in fragment-major fp16 layout: [pass][(ks*8 + j)*32 + lane] -> uint4 (regs b0..b3)
__device__ uint4 g_Bfrag[2][2048];
__device__ __align__(16) float g_sum1[C], g_sq1[C], g_sum2[C], g_sq2[C];
__device__ __align__(16) float g_a1[C], g_c1[C], g_a2[C], g_c2[C];
__device__ int g_is64;

// ---------------- helpers ----------------
typedef unsigned long long ull;
__device__ __forceinline__ uint32_t smem_u32(const void* p) {
    uint32_t a;
    asm("{ .reg .u64 t; cvta.to.shared.u64 t, %1; cvt.u32.u64 %0, t; }" : "=r"(a) : "l"(p));
    return a;
}
__device__ __forceinline__ void ldsm4(uint32_t* r, uint32_t addr) {
    asm volatile("ldmatrix.sync.aligned.m8n8.x4.shared.b16 {%0,%1,%2,%3}, [%4];"
                 : "=r"(r[0]), "=r"(r[1]), "=r"(r[2]), "=r"(r[3]) : "r"(addr));
}
__device__ __forceinline__ void mma16816h(float* d, const uint32_t* a, const uint32_t* b) {
    asm volatile(
        "mma.sync.aligned.m16n8k16.row.col.f32.f16.f16.f32 "
        "{%0,%1,%2,%3}, {%4,%5,%6,%7}, {%8,%9}, {%0,%1,%2,%3};"
        : "+f"(d[0]), "+f"(d[1]), "+f"(d[2]), "+f"(d[3])
        : "r"(a[0]), "r"(a[1]), "r"(a[2]), "r"(a[3]), "r"(b[0]), "r"(b[1]));
}
__device__ __forceinline__ ull pk2(float x, float y) {
    ull r; asm("mov.b64 %0, {%1, %2};" : "=l"(r) : "f"(x), "f"(y)); return r;
}
__device__ __forceinline__ float2 up2(ull v) {
    float2 r; asm("mov.b64 {%0, %1}, %2;" : "=f"(r.x), "=f"(r.y) : "l"(v)); return r;
}
__device__ __forceinline__ ull add2(ull a, ull b) {
    ull r; asm("add.rn.f32x2 %0, %1, %2;" : "=l"(r) : "l"(a), "l"(b)); return r;
}
__device__ __forceinline__ ull fma2(ull a, ull b, ull c) {
    ull r; asm("fma.rn.f32x2 %0, %1, %2, %3;" : "=l"(r) : "l"(a), "l"(b), "l"(c)); return r;
}
__device__ __forceinline__ uint32_t pack_h2(float a, float b) {
    __half2 h = __floats2half2_rn(a, b);
    return *(uint32_t*)&h;
}
__device__ __forceinline__ float2 unpack_h2(uint32_t u) {
    return __half22float2(*(__half2*)&u);
}

// ---- prep: zero stats, sniff edge dtype, pack W1/W2 into fragment-major fp16 ----
__global__ void k_prep(const unsigned* __restrict__ ew,
                       const float* __restrict__ w1, const float* __restrict__ w2) {
    int t = blockIdx.x * 256 + threadIdx.x;       // 0..4095
    if (t < C) { g_sum1[t] = 0.f; g_sq1[t] = 0.f; g_sum2[t] = 0.f; g_sq2[t] = 0.f; }
    if (t == 0) {
        // int64 edge data (non-negative < 2^31) has every odd 32-bit word == 0
        int all0 = 1;
        #pragma unroll
        for (int k = 0; k < 8; k++) all0 &= (ew[2 * k + 1] == 0u);
        g_is64 = all0;
    }
    int p   = t >> 11;            // which weight matrix
    int idx = t & 2047;
    const float* w = p ? w2 : w1;
    int ks = idx >> 8, j = (idx >> 5) & 7, lid = idx & 31;
    int q = lid & 3, nn = lid >> 2;
    uint32_t fr[4];
    #pragma unroll
    for (int r = 0; r < 4; r++) {
        int k = ks * 16 + 2 * q + (r & 1) * 8;
        int n = j * 16 + nn + (r >> 1) * 8;
        fr[r] = pack_h2(w[k * C + n], w[(k + 1) * C + n]);  // smaller k in low 16 bits
    }
    g_Bfrag[p][idx] = make_uint4(fr[0], fr[1], fr[2], fr[3]);
}

// PASS 1: A = x[i]*x[j] (gather), B = w1, D -> h1pre -> g_h (fp16), stats1
// PASS 2: A = relu(a1*g_h + c1),  B = w2, D -> h2pre -> g_h (fp16), stats2
template <int PASS>
__global__ __launch_bounds__(256, 2) void k_pass_mma(
    const float* __restrict__ x, const void* __restrict__ edges_raw,
    const float* __restrict__ bias)
{
    extern __shared__ char sm[];
    const uint32_t sb = smem_u32(sm);
    const int tid = threadIdx.x;
    const int wid = tid >> 5;
    const int lid = tid & 31;
    const int gid = lid >> 2;
    const int tig = lid & 3;
    const int m0 = (wid & 1) * 32;    // warp's 32 rows
    const int n0 = (wid >> 1) * 32;   // warp's 32 cols
    const int jb = (wid >> 1) * 2;    // B n16-chunk base

    float* sBias  = (float*)(sm + SM_BIAS);
    float* sScale = (float*)(sm + SM_SCALE);
    float* sShift = (float*)(sm + SM_SHIFT);
    float* sRed1  = (float*)(sm + SM_RED1);
    float* sRed2  = (float*)(sm + SM_RED2);

    if (tid < C) {
        sBias[tid] = bias[tid];
        sRed1[tid] = 0.f; sRed2[tid] = 0.f;
        if (PASS == 2) { sScale[tid] = g_a1[tid]; sShift[tid] = g_c1[tid]; }
    }
    __syncthreads();

    const int is64 = g_is64;
    const long long* e64 = (const long long*)edges_raw;
    const int*       e32 = (const int*)edges_raw;
    const float4*    x4  = (const float4*)x;
    const uint4* __restrict__ Bf = &g_Bfrag[PASS - 1][0];

    const int rowb = wid;         // prefetch rows rowb + 8i (warp-uniform)
    const int cseg = lid;         // 4-column group

    float4 sc4 = make_float4(0.f,0.f,0.f,0.f), sh4 = sc4;
    if (PASS == 2) {
        sc4 = *(const float4*)&sScale[cseg * 4];
        sh4 = *(const float4*)&sShift[cseg * 4];
    }

    ull s1v[4], s2v[4];
    #pragma unroll
    for (int q = 0; q < 4; q++) { s1v[q] = 0ull; s2v[q] = 0ull; }

    float4 p[8];     // pass-1 prefetch (fp32 gather products)
    uint2  ph[8];    // pass-2 prefetch (fp16 h values)

    #define PREFETCH(tt)                                                            \
        _Pragma("unroll")                                                           \
        for (int i = 0; i < 8; i++) {                                               \
            int e = (tt) * TILE + rowb + 8 * i;                                     \
            if (PASS == 1) {                                                        \
                int ei, ej;                                                         \
                if (is64) { ei = (int)e64[e]; ej = (int)e64[(size_t)E_EDGES + e]; } \
                else      { ei = e32[e];      ej = e32[(size_t)E_EDGES + e]; }      \
                float4 a = x4[(size_t)ei * 32 + cseg];                              \
                float4 b = x4[(size_t)ej * 32 + cseg];                              \
                p[i] = make_float4(a.x*b.x, a.y*b.y, a.z*b.z, a.w*b.w);             \
            } else {                                                                \
                ph[i] = *(const uint2*)&g_h[(size_t)e * C + cseg * 4];              \
            }                                                                       \
        }

    #define STORE_A(bufbase)                                                        \
        _Pragma("unroll")                                                           \
        for (int i = 0; i < 8; i++) {                                               \
            uint32_t u0, u1;                                                        \
            if (PASS == 1) {                                                        \
                u0 = pack_h2(p[i].x, p[i].y);                                       \
                u1 = pack_h2(p[i].z, p[i].w);                                       \
            } else {                                                                \
                float2 lo = unpack_h2(ph[i].x), hi = unpack_h2(ph[i].y);            \
                u0 = pack_h2(fmaxf(fmaf(lo.x, sc4.x, sh4.x), 0.f),                  \
                             fmaxf(fmaf(lo.y, sc4.y, sh4.y), 0.f));                 \
                u1 = pack_h2(fmaxf(fmaf(hi.x, sc4.z, sh4.z), 0.f),                  \
                             fmaxf(fmaf(hi.y, sc4.w, sh4.w), 0.f));                 \
            }                                                                       \
            uint32_t off = (uint32_t)((rowb + 8*i) * PITCHB + cseg * 8);            \
            *(uint2*)(sm + (bufbase) + off) = make_uint2(u0, u1);                   \
        }

    // ---- prologue: fill buffer 0 with tile t0 ----
    const int t0 = blockIdx.x;
    PREFETCH(t0);
    STORE_A(SM_ABUF(0));
    __syncthreads();

    int cur = 0;
    for (int t = t0; t < NTILES; t += gridDim.x) {
        const int e0 = t * TILE;
        const int tn = t + gridDim.x;

        // ---- prefetch next tile into registers (overlaps MMA) ----
        if (tn < NTILES) { PREFETCH(tn); }

        // ---- MMA: D = A*B (single fp16 term); A from smem, B from L2 ----
        const uint32_t aB = sb + SM_ABUF(cur);

        float acc[2][4][4];
        #pragma unroll
        for (int mt = 0; mt < 2; mt++)
            #pragma unroll
            for (int q = 0; q < 4; q++)
                #pragma unroll
                for (int r = 0; r < 4; r++) acc[mt][q][r] = 0.f;

        #pragma unroll
        for (int ks = 0; ks < 8; ks++) {
            uint32_t ah[2][4];
            #pragma unroll
            for (int mb = 0; mb < 2; mb++) {
                uint32_t off = (uint32_t)((m0 + mb*16 + (lid & 15)) * PITCHB
                                          + (ks*16 + (lid >> 4) * 8) * 2);
                ldsm4(ah[mb], aB + off);
            }
            #pragma unroll
            for (int nb2 = 0; nb2 < 2; nb2++) {
                uint4 bv = Bf[(ks * 8 + jb + nb2) * 32 + lid];
                const uint32_t* b = (const uint32_t*)&bv;
                mma16816h(acc[0][2*nb2],   ah[0], b);
                mma16816h(acc[1][2*nb2],   ah[1], b);
                mma16816h(acc[0][2*nb2+1], ah[0], b+2);
                mma16816h(acc[1][2*nb2+1], ah[1], b+2);
            }
        }

        // ---- epilogue: +bias (fp32), fp16 STG to scratch, fp32 stats ----
        #pragma unroll
        for (int q = 0; q < 4; q++) {
            int c0 = n0 + (q >> 1) * 16 + (q & 1) * 8 + 2 * tig;
            float2 bb = *(const float2*)&sBias[c0];
            #pragma unroll
            for (int mt = 0; mt < 2; mt++) {
                int r = m0 + mt * 16 + gid;
                float f0 = acc[mt][q][0] + bb.x, f1 = acc[mt][q][1] + bb.y;
                float f2 = acc[mt][q][2] + bb.x, f3 = acc[mt][q][3] + bb.y;
                *(uint32_t*)&g_h[(size_t)(e0 + r) * C + c0]     = pack_h2(f0, f1);
                *(uint32_t*)&g_h[(size_t)(e0 + r + 8) * C + c0] = pack_h2(f2, f3);
                ull v0 = pk2(f0, f1), v1 = pk2(f2, f3);
                s1v[q] = add2(s1v[q], v0);  s1v[q] = add2(s1v[q], v1);
                s2v[q] = fma2(v0, v0, s2v[q]);  s2v[q] = fma2(v1, v1, s2v[q]);
            }
        }

        // ---- write next tile's A into the other buffer, single barrier ----
        if (tn < NTILES) { STORE_A(SM_ABUF(cur ^ 1)); }
        __syncthreads();
        cur ^= 1;
    }

    // ---- stats: reduce over gid (xor-shuffles), then shared, then global ----
    #pragma unroll
    for (int q = 0; q < 4; q++) {
        float2 a = up2(s1v[q]), b = up2(s2v[q]);
        #pragma unroll
        for (int msk = 4; msk <= 16; msk <<= 1) {
            a.x += __shfl_xor_sync(0xffffffffu, a.x, msk);
            a.y += __shfl_xor_sync(0xffffffffu, a.y, msk);
            b.x += __shfl_xor_sync(0xffffffffu, b.x, msk);
            b.y += __shfl_xor_sync(0xffffffffu, b.y, msk);
        }
        if (gid == 0) {
            int c0 = n0 + (q >> 1) * 16 + (q & 1) * 8 + 2 * tig;
            atomicAdd(&sRed1[c0], a.x);  atomicAdd(&sRed1[c0+1], a.y);
            atomicAdd(&sRed2[c0], b.x);  atomicAdd(&sRed2[c0+1], b.y);
        }
    }
    __syncthreads();
    if (tid < C) {
        atomicAdd((PASS == 1 ? g_sum1 : g_sum2) + tid, sRed1[tid]);
        atomicAdd((PASS == 1 ? g_sq1 : g_sq2) + tid, sRed2[tid]);
    }
}

__global__ void k_fin(const float* __restrict__ g, const float* __restrict__ be, int which) {
    int c = threadIdx.x;
    float sum = which ? g_sum2[c] : g_sum1[c];
    float sq  = which ? g_sq2[c]  : g_sq1[c];
    float mean = sum * (1.f / E_EDGES);
    float var  = sq * (1.f / E_EDGES) - mean * mean;
    float a = g[c] * rsqrtf(var + BN_EPS);
    float cc = be[c] - mean * a;
    if (which) { g_a2[c] = a; g_c2[c] = cc; }
    else       { g_a1[c] = a; g_c1[c] = cc; }
}

__global__ __launch_bounds__(256) void k_out(const float* __restrict__ wc,
                                             const float* __restrict__ bc,
                                             float* __restrict__ out)
{
    const int lane = threadIdx.x & 31;
    const int warp = threadIdx.x >> 5;
    const int nwarp = gridDim.x * 8;
    const int wg = blockIdx.x * 8 + warp;

    float4 a2 = *(const float4*)&g_a2[lane * 4];
    float4 c2 = *(const float4*)&g_c2[lane * 4];
    float4 wv = *(const float4*)&wc[lane * 4];
    float b = bc[0];

    for (size_t e = wg; e < E_EDGES; e += nwarp) {
        uint2 hv = *(const uint2*)&g_h[e * C + lane * 4];
        float2 v01 = unpack_h2(hv.x), v23 = unpack_h2(hv.y);
        float r = fmaxf(fmaf(v01.x, a2.x, c2.x), 0.f) * wv.x
                + fmaxf(fmaf(v01.y, a2.y, c2.y), 0.f) * wv.y
                + fmaxf(fmaf(v23.x, a2.z, c2.z), 0.f) * wv.z
                + fmaxf(fmaf(v23.y, a2.w, c2.w), 0.f) * wv.w;
        #pragma unroll
        for (int s = 16; s > 0; s >>= 1) r += __shfl_xor_sync(0xffffffffu, r, s);
        if (lane == 0) out[e] = r + b;
    }
}

extern "C" void kernel_launch(void* const* d_in, const int* in_sizes, int n_in,
                              void* d_out, int out_size) {
    const float* x     = (const float*)d_in[0];
    const void*  edges = d_in[1];
    const float* w1    = (const float*)d_in[2];
    const float* b1    = (const float*)d_in[3];
    const float* g1    = (const float*)d_in[4];
    const float* be1   = (const float*)d_in[5];
    const float* w2    = (const float*)d_in[6];
    const float* b2    = (const float*)d_in[7];
    const float* g2    = (const float*)d_in[8];
    const float* be2   = (const float*)d_in[9];
    const float* wc    = (const float*)d_in[10];
    const float* bc    = (const float*)d_in[11];
    float* out = (float*)d_out;
    (void)in_sizes; (void)n_in; (void)out_size;

    cudaFuncSetAttribute(k_pass_mma<1>, cudaFuncAttributeMaxDynamicSharedMemorySize, SM_TOTAL);
    cudaFuncSetAttribute(k_pass_mma<2>, cudaFuncAttributeMaxDynamicSharedMemorySize, SM_TOTAL);

    k_prep<<<16, 256>>>((const unsigned*)edges, w1, w2);
    k_pass_mma<1><<<296, 256, SM_TOTAL>>>(x, edges, b1);
    k_fin<<<1, 128>>>(g1, be1, 0);
    k_pass_mma<2><<<296, 256, SM_TOTAL>>>(x, edges, b2);
    k_fin<<<1, 128>>>(g2, be2, 1);
    k_out<<<2048, 256>>>(wc, bc, out);
}

// round 15
// speedup vs baseline: 2.6041x; 1.0367x over previous
#include <cuda_runtime.h>
#include <cuda_fp16.h>
#include <cstdint>

#define C 128
#define NNODES 100000
#define E_EDGES 1000000
#define TILE 64
#define NTILES (E_EDGES / TILE)   // 15625 exact
#define BN_EPS 1e-5f
#define PITCHB 272   // bytes per fp16 A-tile row (136 halves: 128 data + 8 pad)

// ---------------- SMEM layout: A (fp16, single-plane) double-buffered ----------------
#define SM_ABUF(b) ((b) * 17408)
#define SM_BIAS  34816   // float[128]
#define SM_SCALE 35328   // float[128]
#define SM_SHIFT 35840   // float[128]
#define SM_RED1  36352   // float[128]
#define SM_RED2  36864   // float[128]
#define SM_TOTAL 37376

// 256 MB fp16 scratch for h1pre (pass1 -> pass2) then h2pre (pass2 -> out), in place.
__device__ __half g_h[(size_t)E_EDGES * C];
// fp16 copy of x (gather source), 25.6 MB
__device__ __align__(16) __half g_xh[(size_t)NNODES * C];
// B in fragment-major fp16 layout: [pass][(ks*8 + j)*32 + lane] -> uint4 (regs b0..b3)
__device__ uint4 g_Bfrag[2][2048];
__device__ __align__(16) float g_sum1[C], g_sq1[C], g_sum2[C], g_sq2[C];
__device__ __align__(16) float g_a1[C], g_c1[C], g_a2[C], g_c2[C];
__device__ int g_is64;

// ---------------- helpers ----------------
typedef unsigned long long ull;
__device__ __forceinline__ uint32_t smem_u32(const void* p) {
    uint32_t a;
    asm("{ .reg .u64 t; cvta.to.shared.u64 t, %1; cvt.u32.u64 %0, t; }" : "=r"(a) : "l"(p));
    return a;
}
__device__ __forceinline__ void ldsm4(uint32_t* r, uint32_t addr) {
    asm volatile("ldmatrix.sync.aligned.m8n8.x4.shared.b16 {%0,%1,%2,%3}, [%4];"
                 : "=r"(r[0]), "=r"(r[1]), "=r"(r[2]), "=r"(r[3]) : "r"(addr));
}
__device__ __forceinline__ void mma16816h(float* d, const uint32_t* a, const uint32_t* b) {
    asm volatile(
        "mma.sync.aligned.m16n8k16.row.col.f32.f16.f16.f32 "
        "{%0,%1,%2,%3}, {%4,%5,%6,%7}, {%8,%9}, {%0,%1,%2,%3};"
        : "+f"(d[0]), "+f"(d[1]), "+f"(d[2]), "+f"(d[3])
        : "r"(a[0]), "r"(a[1]), "r"(a[2]), "r"(a[3]), "r"(b[0]), "r"(b[1]));
}
__device__ __forceinline__ ull pk2(float x, float y) {
    ull r; asm("mov.b64 %0, {%1, %2};" : "=l"(r) : "f"(x), "f"(y)); return r;
}
__device__ __forceinline__ float2 up2(ull v) {
    float2 r; asm("mov.b64 {%0, %1}, %2;" : "=f"(r.x), "=f"(r.y) : "l"(v)); return r;
}
__device__ __forceinline__ ull add2(ull a, ull b) {
    ull r; asm("add.rn.f32x2 %0, %1, %2;" : "=l"(r) : "l"(a), "l"(b)); return r;
}
__device__ __forceinline__ ull fma2(ull a, ull b, ull c) {
    ull r; asm("fma.rn.f32x2 %0, %1, %2, %3;" : "=l"(r) : "l"(a), "l"(b), "l"(c)); return r;
}
__device__ __forceinline__ uint32_t pack_h2(float a, float b) {
    __half2 h = __floats2half2_rn(a, b);
    return *(uint32_t*)&h;
}
__device__ __forceinline__ float2 unpack_h2(uint32_t u) {
    return __half22float2(*(__half2*)&u);
}
__device__ __forceinline__ uint32_t hmul2u(uint32_t a, uint32_t b) {
    __half2 r = __hmul2(*(__half2*)&a, *(__half2*)&b);
    return *(uint32_t*)&r;
}
__device__ __forceinline__ uint32_t hfma2relu(uint32_t h, uint32_t s, uint32_t c) {
    __half2 r = __hfma2_relu(*(__half2*)&h, *(__half2*)&s, *(__half2*)&c);
    return *(uint32_t*)&r;
}

// ---- quantize x to fp16 ----
__global__ void k_quant(const float* __restrict__ x) {
    size_t i = (size_t)blockIdx.x * 256 + threadIdx.x;
    const size_t total = (size_t)NNODES * C / 8;     // uint4 outputs
    for (; i < total; i += (size_t)gridDim.x * 256) {
        const float4* src = (const float4*)x + i * 2;
        float4 a = src[0], b = src[1];
        uint4 o;
        o.x = pack_h2(a.x, a.y); o.y = pack_h2(a.z, a.w);
        o.z = pack_h2(b.x, b.y); o.w = pack_h2(b.z, b.w);
        ((uint4*)g_xh)[i] = o;
    }
}

// ---- prep: zero stats, sniff edge dtype, pack W1/W2 into fragment-major fp16 ----
__global__ void k_prep(const unsigned* __restrict__ ew,
                       const float* __restrict__ w1, const float* __restrict__ w2) {
    int t = blockIdx.x * 256 + threadIdx.x;       // 0..4095
    if (t < C) { g_sum1[t] = 0.f; g_sq1[t] = 0.f; g_sum2[t] = 0.f; g_sq2[t] = 0.f; }
    if (t == 0) {
        // int64 edge data (non-negative < 2^31) has every odd 32-bit word == 0
        int all0 = 1;
        #pragma unroll
        for (int k = 0; k < 8; k++) all0 &= (ew[2 * k + 1] == 0u);
        g_is64 = all0;
    }
    int p   = t >> 11;            // which weight matrix
    int idx = t & 2047;
    const float* w = p ? w2 : w1;
    int ks = idx >> 8, j = (idx >> 5) & 7, lid = idx & 31;
    int q = lid & 3, nn = lid >> 2;
    uint32_t fr[4];
    #pragma unroll
    for (int r = 0; r < 4; r++) {
        int k = ks * 16 + 2 * q + (r & 1) * 8;
        int n = j * 16 + nn + (r >> 1) * 8;
        fr[r] = pack_h2(w[k * C + n], w[(k + 1) * C + n]);  // smaller k in low 16 bits
    }
    g_Bfrag[p][idx] = make_uint4(fr[0], fr[1], fr[2], fr[3]);
}

// PASS 1: A = x[i]*x[j] (fp16 gather), B = w1, D -> h1pre -> g_h (fp16), stats1
// PASS 2: A = relu(a1*g_h + c1) (half2), B = w2, D -> h2pre -> g_h (fp16), stats2
template <int PASS>
__global__ __launch_bounds__(256, 2) void k_pass_mma(
    const void* __restrict__ edges_raw, const float* __restrict__ bias)
{
    extern __shared__ char sm[];
    const uint32_t sb = smem_u32(sm);
    const int tid = threadIdx.x;
    const int wid = tid >> 5;
    const int lid = tid & 31;
    const int gid = lid >> 2;
    const int tig = lid & 3;
    const int m0 = (wid & 1) * 32;    // warp's 32 rows
    const int n0 = (wid >> 1) * 32;   // warp's 32 cols
    const int jb = (wid >> 1) * 2;    // B n16-chunk base

    float* sBias  = (float*)(sm + SM_BIAS);
    float* sScale = (float*)(sm + SM_SCALE);
    float* sShift = (float*)(sm + SM_SHIFT);
    float* sRed1  = (float*)(sm + SM_RED1);
    float* sRed2  = (float*)(sm + SM_RED2);

    if (tid < C) {
        sBias[tid] = bias[tid];
        sRed1[tid] = 0.f; sRed2[tid] = 0.f;
        if (PASS == 2) { sScale[tid] = g_a1[tid]; sShift[tid] = g_c1[tid]; }
    }
    __syncthreads();

    const int is64 = g_is64;
    const long long* e64 = (const long long*)edges_raw;
    const int*       e32 = (const int*)edges_raw;
    const uint4*     xh4 = (const uint4*)g_xh;     // 16 uint4 per node row
    const uint4* __restrict__ Bf = &g_Bfrag[PASS - 1][0];

    // A-build mapping: 8-col segments; warp covers 2 rows per iter, 4 iters
    const int arow = wid * 8 + (lid >> 4);   // rows arow + 2i
    const int aseg = lid & 15;               // uint4 segment (8 halves)

    uint32_t sc2[4], sh2[4];
    if (PASS == 2) {
        #pragma unroll
        for (int k = 0; k < 4; k++) {
            int c = aseg * 8 + 2 * k;
            sc2[k] = pack_h2(sScale[c], sScale[c + 1]);
            sh2[k] = pack_h2(sShift[c], sShift[c + 1]);
        }
    }

    ull s1v[4], s2v[4];
    #pragma unroll
    for (int q = 0; q < 4; q++) { s1v[q] = 0ull; s2v[q] = 0ull; }

    uint4 pr[4];

    #define PREFETCH(tt)                                                            \
        _Pragma("unroll")                                                           \
        for (int i = 0; i < 4; i++) {                                               \
            int e = (tt) * TILE + arow + 2 * i;                                     \
            if (PASS == 1) {                                                        \
                int ei, ej;                                                         \
                if (is64) { ei = (int)e64[e]; ej = (int)e64[(size_t)E_EDGES + e]; } \
                else      { ei = e32[e];      ej = e32[(size_t)E_EDGES + e]; }      \
                uint4 xa = xh4[(size_t)ei * 16 + aseg];                             \
                uint4 xb = xh4[(size_t)ej * 16 + aseg];                             \
                pr[i].x = hmul2u(xa.x, xb.x); pr[i].y = hmul2u(xa.y, xb.y);         \
                pr[i].z = hmul2u(xa.z, xb.z); pr[i].w = hmul2u(xa.w, xb.w);         \
            } else {                                                                \
                pr[i] = *(const uint4*)&g_h[(size_t)e * C + aseg * 8];              \
            }                                                                       \
        }

    #define STORE_A(bufbase)                                                        \
        _Pragma("unroll")                                                           \
        for (int i = 0; i < 4; i++) {                                               \
            uint4 v = pr[i];                                                        \
            if (PASS == 2) {                                                        \
                v.x = hfma2relu(v.x, sc2[0], sh2[0]);                               \
                v.y = hfma2relu(v.y, sc2[1], sh2[1]);                               \
                v.z = hfma2relu(v.z, sc2[2], sh2[2]);                               \
                v.w = hfma2relu(v.w, sc2[3], sh2[3]);                               \
            }                                                                       \
            uint32_t off = (uint32_t)((arow + 2*i) * PITCHB + aseg * 16);           \
            *(uint4*)(sm + (bufbase) + off) = v;                                    \
        }

    // ---- prologue: fill buffer 0 with tile t0 ----
    const int t0 = blockIdx.x;
    PREFETCH(t0);
    STORE_A(SM_ABUF(0));
    __syncthreads();

    int cur = 0;
    for (int t = t0; t < NTILES; t += gridDim.x) {
        const int e0 = t * TILE;
        const int tn = t + gridDim.x;

        // ---- prefetch next tile into registers (overlaps MMA) ----
        if (tn < NTILES) { PREFETCH(tn); }

        // ---- MMA: D = A*B (single fp16 term); A from smem, B from L2 ----
        const uint32_t aB = sb + SM_ABUF(cur);

        float acc[2][4][4];
        #pragma unroll
        for (int mt = 0; mt < 2; mt++)
            #pragma unroll
            for (int q = 0; q < 4; q++)
                #pragma unroll
                for (int r = 0; r < 4; r++) acc[mt][q][r] = 0.f;

        #pragma unroll
        for (int ks = 0; ks < 8; ks++) {
            uint32_t ah[2][4];
            #pragma unroll
            for (int mb = 0; mb < 2; mb++) {
                uint32_t off = (uint32_t)((m0 + mb*16 + (lid & 15)) * PITCHB
                                          + (ks*16 + (lid >> 4) * 8) * 2);
                ldsm4(ah[mb], aB + off);
            }
            #pragma unroll
            for (int nb2 = 0; nb2 < 2; nb2++) {
                uint4 bv = Bf[(ks * 8 + jb + nb2) * 32 + lid];
                const uint32_t* b = (const uint32_t*)&bv;
                mma16816h(acc[0][2*nb2],   ah[0], b);
                mma16816h(acc[1][2*nb2],   ah[1], b);
                mma16816h(acc[0][2*nb2+1], ah[0], b+2);
                mma16816h(acc[1][2*nb2+1], ah[1], b+2);
            }
        }

        // ---- epilogue: +bias (fp32), fp16 STG to scratch, fp32 stats ----
        #pragma unroll
        for (int q = 0; q < 4; q++) {
            int c0 = n0 + (q >> 1) * 16 + (q & 1) * 8 + 2 * tig;
            float2 bb = *(const float2*)&sBias[c0];
            #pragma unroll
            for (int mt = 0; mt < 2; mt++) {
                int r = m0 + mt * 16 + gid;
                float f0 = acc[mt][q][0] + bb.x, f1 = acc[mt][q][1] + bb.y;
                float f2 = acc[mt][q][2] + bb.x, f3 = acc[mt][q][3] + bb.y;
                *(uint32_t*)&g_h[(size_t)(e0 + r) * C + c0]     = pack_h2(f0, f1);
                *(uint32_t*)&g_h[(size_t)(e0 + r + 8) * C + c0] = pack_h2(f2, f3);
                ull v0 = pk2(f0, f1), v1 = pk2(f2, f3);
                s1v[q] = add2(s1v[q], v0);  s1v[q] = add2(s1v[q], v1);
                s2v[q] = fma2(v0, v0, s2v[q]);  s2v[q] = fma2(v1, v1, s2v[q]);
            }
        }

        // ---- write next tile's A into the other buffer, single barrier ----
        if (tn < NTILES) { STORE_A(SM_ABUF(cur ^ 1)); }
        __syncthreads();
        cur ^= 1;
    }

    // ---- stats: reduce over gid (xor-shuffles), then shared, then global ----
    #pragma unroll
    for (int q = 0; q < 4; q++) {
        float2 a = up2(s1v[q]), b = up2(s2v[q]);
        #pragma unroll
        for (int msk = 4; msk <= 16; msk <<= 1) {
            a.x += __shfl_xor_sync(0xffffffffu, a.x, msk);
            a.y += __shfl_xor_sync(0xffffffffu, a.y, msk);
            b.x += __shfl_xor_sync(0xffffffffu, b.x, msk);
            b.y += __shfl_xor_sync(0xffffffffu, b.y, msk);
        }
        if (gid == 0) {
            int c0 = n0 + (q >> 1) * 16 + (q & 1) * 8 + 2 * tig;
            atomicAdd(&sRed1[c0], a.x);  atomicAdd(&sRed1[c0+1], a.y);
            atomicAdd(&sRed2[c0], b.x);  atomicAdd(&sRed2[c0+1], b.y);
        }
    }
    __syncthreads();
    if (tid < C) {
        atomicAdd((PASS == 1 ? g_sum1 : g_sum2) + tid, sRed1[tid]);
        atomicAdd((PASS == 1 ? g_sq1 : g_sq2) + tid, sRed2[tid]);
    }
}

__global__ void k_fin(const float* __restrict__ g, const float* __restrict__ be, int which) {
    int c = threadIdx.x;
    float sum = which ? g_sum2[c] : g_sum1[c];
    float sq  = which ? g_sq2[c]  : g_sq1[c];
    float mean = sum * (1.f / E_EDGES);
    float var  = sq * (1.f / E_EDGES) - mean * mean;
    float a = g[c] * rsqrtf(var + BN_EPS);
    float cc = be[c] - mean * a;
    if (which) { g_a2[c] = a; g_c2[c] = cc; }
    else       { g_a1[c] = a; g_c1[c] = cc; }
}

__global__ __launch_bounds__(256) void k_out(const float* __restrict__ wc,
                                             const float* __restrict__ bc,
                                             float* __restrict__ out)
{
    const int lane = threadIdx.x & 31;
    const int warp = threadIdx.x >> 5;
    const int nwarp = gridDim.x * 8;
    const int wg = blockIdx.x * 8 + warp;

    float4 a2 = *(const float4*)&g_a2[lane * 4];
    float4 c2 = *(const float4*)&g_c2[lane * 4];
    float4 wv = *(const float4*)&wc[lane * 4];
    float b = bc[0];

    for (size_t e = wg; e < E_EDGES; e += nwarp) {
        uint2 hv = *(const uint2*)&g_h[e * C + lane * 4];
        float2 v01 = unpack_h2(hv.x), v23 = unpack_h2(hv.y);
        float r = fmaxf(fmaf(v01.x, a2.x, c2.x), 0.f) * wv.x
                + fmaxf(fmaf(v01.y, a2.y, c2.y), 0.f) * wv.y
                + fmaxf(fmaf(v23.x, a2.z, c2.z), 0.f) * wv.z
                + fmaxf(fmaf(v23.y, a2.w, c2.w), 0.f) * wv.w;
        #pragma unroll
        for (int s = 16; s > 0; s >>= 1) r += __shfl_xor_sync(0xffffffffu, r, s);
        if (lane == 0) out[e] = r + b;
    }
}

extern "C" void kernel_launch(void* const* d_in, const int* in_sizes, int n_in,
                              void* d_out, int out_size) {
    const float* x     = (const float*)d_in[0];
    const void*  edges = d_in[1];
    const float* w1    = (const float*)d_in[2];
    const float* b1    = (const float*)d_in[3];
    const float* g1    = (const float*)d_in[4];
    const float* be1   = (const float*)d_in[5];
    const float* w2    = (const float*)d_in[6];
    const float* b2    = (const float*)d_in[7];
    const float* g2    = (const float*)d_in[8];
    const float* be2   = (const float*)d_in[9];
    const float* wc    = (const float*)d_in[10];
    const float* bc    = (const float*)d_in[11];
    float* out = (float*)d_out;
    (void)in_sizes; (void)n_in; (void)out_size;

    cudaFuncSetAttribute(k_pass_mma<1>, cudaFuncAttributeMaxDynamicSharedMemorySize, SM_TOTAL);
    cudaFuncSetAttribute(k_pass_mma<2>, cudaFuncAttributeMaxDynamicSharedMemorySize, SM_TOTAL);

    k_quant<<<2048, 256>>>(x);
    k_prep<<<16, 256>>>((const unsigned*)edges, w1, w2);
    k_pass_mma<1><<<296, 256, SM_TOTAL>>>(edges, b1);
    k_fin<<<1, 128>>>(g1, be1, 0);
    k_pass_mma<2><<<296, 256, SM_TOTAL>>>(edges, b2);
    k_fin<<<1, 128>>>(g2, be2, 1);
    k_out<<<2048, 256>>>(wc, bc, out);
}

// round 16
// speedup vs baseline: 2.6692x; 1.0250x over previous
#include <cuda_runtime.h>
#include <cuda_fp16.h>
#include <cstdint>

#define C 128
#define NNODES 100000
#define E_EDGES 1000000
#define TILE 64
#define NTILES (E_EDGES / TILE)   // 15625 exact
#define BN_EPS 1e-5f
#define PITCHB 272   // bytes per fp16 A-tile row (136 halves: 128 data + 8 pad)

// ---------------- SMEM layout ----------------
#define SM_ABUF(b) ((b) * 17408)   // pass1 A double-buffer
#define SM_SCSH  34816   // pass2: uint4[32] BN scale/shift LUT (512 B)
#define SM_BIAS  35328   // float[128]
#define SM_SCALE 35840   // float[128]
#define SM_SHIFT 36352   // float[128]
#define SM_RED1  36864   // float[128]
#define SM_RED2  37376   // float[128]
#define SM_TOTAL 37888

// 256 MB fp16 scratch, FRAGMENT-MAJOR:
// block(t, mi, ks) = t*32 + mi*8 + ks   (mi = m-16tile 0..3, ks = k-16chunk 0..7)
// uint4 index = block*32 + lane;  uint4 = {a0,a1,a2,a3} of the m16k16 A fragment.
__device__ uint4 g_h4[(size_t)NTILES * 32 * 32];
// fp16 copy of x (gather source), 25.6 MB
__device__ __align__(16) __half g_xh[(size_t)NNODES * C];
// B in fragment-major fp16 layout: [pass][(ks*8 + j)*32 + lane] -> uint4
__device__ uint4 g_Bfrag[2][2048];
__device__ __align__(16) float g_sum1[C], g_sq1[C], g_sum2[C], g_sq2[C];
__device__ __align__(16) float g_a1[C], g_c1[C], g_a2[C], g_c2[C];
__device__ int g_is64;

// ---------------- helpers ----------------
typedef unsigned long long ull;
__device__ __forceinline__ uint32_t smem_u32(const void* p) {
    uint32_t a;
    asm("{ .reg .u64 t; cvta.to.shared.u64 t, %1; cvt.u32.u64 %0, t; }" : "=r"(a) : "l"(p));
    return a;
}
__device__ __forceinline__ void ldsm4(uint32_t* r, uint32_t addr) {
    asm volatile("ldmatrix.sync.aligned.m8n8.x4.shared.b16 {%0,%1,%2,%3}, [%4];"
                 : "=r"(r[0]), "=r"(r[1]), "=r"(r[2]), "=r"(r[3]) : "r"(addr));
}
__device__ __forceinline__ void mma16816h(float* d, const uint32_t* a, const uint32_t* b) {
    asm volatile(
        "mma.sync.aligned.m16n8k16.row.col.f32.f16.f16.f32 "
        "{%0,%1,%2,%3}, {%4,%5,%6,%7}, {%8,%9}, {%0,%1,%2,%3};"
        : "+f"(d[0]), "+f"(d[1]), "+f"(d[2]), "+f"(d[3])
        : "r"(a[0]), "r"(a[1]), "r"(a[2]), "r"(a[3]), "r"(b[0]), "r"(b[1]));
}
__device__ __forceinline__ ull pk2(float x, float y) {
    ull r; asm("mov.b64 %0, {%1, %2};" : "=l"(r) : "f"(x), "f"(y)); return r;
}
__device__ __forceinline__ float2 up2(ull v) {
    float2 r; asm("mov.b64 {%0, %1}, %2;" : "=f"(r.x), "=f"(r.y) : "l"(v)); return r;
}
__device__ __forceinline__ ull add2(ull a, ull b) {
    ull r; asm("add.rn.f32x2 %0, %1, %2;" : "=l"(r) : "l"(a), "l"(b)); return r;
}
__device__ __forceinline__ ull fma2(ull a, ull b, ull c) {
    ull r; asm("fma.rn.f32x2 %0, %1, %2, %3;" : "=l"(r) : "l"(a), "l"(b), "l"(c)); return r;
}
__device__ __forceinline__ uint32_t pack_h2(float a, float b) {
    __half2 h = __floats2half2_rn(a, b);
    return *(uint32_t*)&h;
}
__device__ __forceinline__ float2 unpack_h2(uint32_t u) {
    return __half22float2(*(__half2*)&u);
}
__device__ __forceinline__ uint32_t hmul2u(uint32_t a, uint32_t b) {
    __half2 r = __hmul2(*(__half2*)&a, *(__half2*)&b);
    return *(uint32_t*)&r;
}
__device__ __forceinline__ uint32_t hfma2relu(uint32_t h, uint32_t s, uint32_t c) {
    __half2 r = __hfma2_relu(*(__half2*)&h, *(__half2*)&s, *(__half2*)&c);
    return *(uint32_t*)&r;
}

// ---- quantize x to fp16 ----
__global__ void k_quant(const float* __restrict__ x) {
    size_t i = (size_t)blockIdx.x * 256 + threadIdx.x;
    const size_t total = (size_t)NNODES * C / 8;
    for (; i < total; i += (size_t)gridDim.x * 256) {
        const float4* src = (const float4*)x + i * 2;
        float4 a = src[0], b = src[1];
        uint4 o;
        o.x = pack_h2(a.x, a.y); o.y = pack_h2(a.z, a.w);
        o.z = pack_h2(b.x, b.y); o.w = pack_h2(b.z, b.w);
        ((uint4*)g_xh)[i] = o;
    }
}

// ---- prep: zero stats, sniff edge dtype, pack W1/W2 into fragment-major fp16 ----
__global__ void k_prep(const unsigned* __restrict__ ew,
                       const float* __restrict__ w1, const float* __restrict__ w2) {
    int t = blockIdx.x * 256 + threadIdx.x;       // 0..4095
    if (t < C) { g_sum1[t] = 0.f; g_sq1[t] = 0.f; g_sum2[t] = 0.f; g_sq2[t] = 0.f; }
    if (t == 0) {
        int all0 = 1;
        #pragma unroll
        for (int k = 0; k < 8; k++) all0 &= (ew[2 * k + 1] == 0u);
        g_is64 = all0;
    }
    int p   = t >> 11;
    int idx = t & 2047;
    const float* w = p ? w2 : w1;
    int ks = idx >> 8, j = (idx >> 5) & 7, lid = idx & 31;
    int q = lid & 3, nn = lid >> 2;
    uint32_t fr[4];
    #pragma unroll
    for (int r = 0; r < 4; r++) {
        int k = ks * 16 + 2 * q + (r & 1) * 8;
        int n = j * 16 + nn + (r >> 1) * 8;
        fr[r] = pack_h2(w[k * C + n], w[(k + 1) * C + n]);
    }
    g_Bfrag[p][idx] = make_uint4(fr[0], fr[1], fr[2], fr[3]);
}

// PASS 1: A = x[i]*x[j] (fp16 gather via smem+ldsm), D -> h1 fragments, stats1
// PASS 2: A = relu(a1*h1+c1) on fragments straight from gmem, D -> h2 fragments, stats2
template <int PASS>
__global__ __launch_bounds__(256, 2) void k_pass_mma(
    const void* __restrict__ edges_raw, const float* __restrict__ bias)
{
    extern __shared__ char sm[];
    const uint32_t sb = smem_u32(sm);
    const int tid = threadIdx.x;
    const int wid = tid >> 5;
    const int lid = tid & 31;
    const int gid = lid >> 2;
    const int tig = lid & 3;
    const int m0 = (wid & 1) * 32;
    const int n0 = (wid >> 1) * 32;
    const int jb = (wid >> 1) * 2;
    const int miB = (wid & 1) * 2;    // m-16tile base

    float* sBias  = (float*)(sm + SM_BIAS);
    float* sScale = (float*)(sm + SM_SCALE);
    float* sShift = (float*)(sm + SM_SHIFT);
    float* sRed1  = (float*)(sm + SM_RED1);
    float* sRed2  = (float*)(sm + SM_RED2);
    uint4* sScSh  = (uint4*)(sm + SM_SCSH);

    if (tid < C) {
        sBias[tid] = bias[tid];
        sRed1[tid] = 0.f; sRed2[tid] = 0.f;
        if (PASS == 2) { sScale[tid] = g_a1[tid]; sShift[tid] = g_c1[tid]; }
    }
    __syncthreads();
    if (PASS == 2 && tid < 32) {
        int ks = tid >> 2, tg = tid & 3;
        int cl = ks * 16 + 2 * tg, ch = cl + 8;
        sScSh[tid] = make_uint4(pack_h2(sScale[cl], sScale[cl + 1]),
                                pack_h2(sScale[ch], sScale[ch + 1]),
                                pack_h2(sShift[cl], sShift[cl + 1]),
                                pack_h2(sShift[ch], sShift[ch + 1]));
    }
    if (PASS == 2) __syncthreads();

    const int is64 = g_is64;
    const long long* e64 = (const long long*)edges_raw;
    const int*       e32 = (const int*)edges_raw;
    const uint4*     xh4 = (const uint4*)g_xh;
    const uint4* __restrict__ Bf = &g_Bfrag[PASS - 1][0];

    // pass-1 A-build mapping
    const int arow = wid * 8 + (lid >> 4);
    const int aseg = lid & 15;

    ull s1v[4], s2v[4];
    #pragma unroll
    for (int q = 0; q < 4; q++) { s1v[q] = 0ull; s2v[q] = 0ull; }

    uint4 pr[4];

    #define PREFETCH(tt)                                                            \
        _Pragma("unroll")                                                           \
        for (int i = 0; i < 4; i++) {                                               \
            int e = (tt) * TILE + arow + 2 * i;                                     \
            int ei, ej;                                                             \
            if (is64) { ei = (int)e64[e]; ej = (int)e64[(size_t)E_EDGES + e]; }     \
            else      { ei = e32[e];      ej = e32[(size_t)E_EDGES + e]; }          \
            uint4 xa = xh4[(size_t)ei * 16 + aseg];                                 \
            uint4 xb = xh4[(size_t)ej * 16 + aseg];                                 \
            pr[i].x = hmul2u(xa.x, xb.x); pr[i].y = hmul2u(xa.y, xb.y);             \
            pr[i].z = hmul2u(xa.z, xb.z); pr[i].w = hmul2u(xa.w, xb.w);             \
        }

    #define STORE_A(bufbase)                                                        \
        _Pragma("unroll")                                                           \
        for (int i = 0; i < 4; i++) {                                               \
            uint32_t off = (uint32_t)((arow + 2*i) * PITCHB + aseg * 16);           \
            *(uint4*)(sm + (bufbase) + off) = pr[i];                                \
        }

    // epilogue: +bias, stats, fragment-major uint4 store
    #define EPILOGUE(tt)                                                            \
        _Pragma("unroll")                                                           \
        for (int mt = 0; mt < 2; mt++) {                                            \
            int mi = miB + mt;                                                      \
            _Pragma("unroll")                                                       \
            for (int jj = 0; jj < 2; jj++) {                                        \
                int q0 = 2*jj, q1 = 2*jj + 1;                                       \
                int c0 = n0 + jj*16 + 2*tig;                                        \
                float2 bb0 = *(const float2*)&sBias[c0];                            \
                float2 bb1 = *(const float2*)&sBias[c0 + 8];                        \
                float f00 = acc[mt][q0][0]+bb0.x, f01 = acc[mt][q0][1]+bb0.y;       \
                float f02 = acc[mt][q0][2]+bb0.x, f03 = acc[mt][q0][3]+bb0.y;       \
                float f10 = acc[mt][q1][0]+bb1.x, f11 = acc[mt][q1][1]+bb1.y;       \
                float f12 = acc[mt][q1][2]+bb1.x, f13 = acc[mt][q1][3]+bb1.y;       \
                ull v0 = pk2(f00, f01), v1 = pk2(f02, f03);                         \
                ull v2 = pk2(f10, f11), v3 = pk2(f12, f13);                         \
                s1v[q0] = add2(s1v[q0], v0);  s1v[q0] = add2(s1v[q0], v1);          \
                s2v[q0] = fma2(v0, v0, s2v[q0]);  s2v[q0] = fma2(v1, v1, s2v[q0]);  \
                s1v[q1] = add2(s1v[q1], v2);  s1v[q1] = add2(s1v[q1], v3);          \
                s2v[q1] = fma2(v2, v2, s2v[q1]);  s2v[q1] = fma2(v3, v3, s2v[q1]);  \
                int ksg = jb + jj;                                                  \
                g_h4[(size_t)((tt)*32 + mi*8 + ksg)*32 + lid] =                     \
                    make_uint4(pack_h2(f00,f01), pack_h2(f02,f03),                  \
                               pack_h2(f10,f11), pack_h2(f12,f13));                 \
            }                                                                       \
        }

    if (PASS == 1) {
        const int t0 = blockIdx.x;
        PREFETCH(t0);
        STORE_A(SM_ABUF(0));
        __syncthreads();

        int cur = 0;
        for (int t = t0; t < NTILES; t += gridDim.x) {
            const int tn = t + gridDim.x;
            if (tn < NTILES) { PREFETCH(tn); }

            const uint32_t aB = sb + SM_ABUF(cur);
            float acc[2][4][4];
            #pragma unroll
            for (int mt = 0; mt < 2; mt++)
                #pragma unroll
                for (int q = 0; q < 4; q++)
                    #pragma unroll
                    for (int r = 0; r < 4; r++) acc[mt][q][r] = 0.f;

            #pragma unroll
            for (int ks = 0; ks < 8; ks++) {
                uint32_t ah[2][4];
                #pragma unroll
                for (int mb = 0; mb < 2; mb++) {
                    uint32_t off = (uint32_t)((m0 + mb*16 + (lid & 15)) * PITCHB
                                              + (ks*16 + (lid >> 4) * 8) * 2);
                    ldsm4(ah[mb], aB + off);
                }
                #pragma unroll
                for (int nb2 = 0; nb2 < 2; nb2++) {
                    uint4 bv = Bf[(ks * 8 + jb + nb2) * 32 + lid];
                    const uint32_t* b = (const uint32_t*)&bv;
                    mma16816h(acc[0][2*nb2],   ah[0], b);
                    mma16816h(acc[1][2*nb2],   ah[1], b);
                    mma16816h(acc[0][2*nb2+1], ah[0], b+2);
                    mma16816h(acc[1][2*nb2+1], ah[1], b+2);
                }
            }

            EPILOGUE(t);
            if (tn < NTILES) { STORE_A(SM_ABUF(cur ^ 1)); }
            __syncthreads();
            cur ^= 1;
        }
    } else {
        for (int t = blockIdx.x; t < NTILES; t += gridDim.x) {
            float acc[2][4][4];
            #pragma unroll
            for (int mt = 0; mt < 2; mt++)
                #pragma unroll
                for (int q = 0; q < 4; q++)
                    #pragma unroll
                    for (int r = 0; r < 4; r++) acc[mt][q][r] = 0.f;

            #pragma unroll
            for (int ks = 0; ks < 8; ks++) {
                uint4 s = sScSh[ks * 4 + tig];
                uint4 a[2];
                #pragma unroll
                for (int mb = 0; mb < 2; mb++) {
                    uint4 v = g_h4[(size_t)(t*32 + (miB + mb)*8 + ks)*32 + lid];
                    v.x = hfma2relu(v.x, s.x, s.z);
                    v.y = hfma2relu(v.y, s.x, s.z);
                    v.z = hfma2relu(v.z, s.y, s.w);
                    v.w = hfma2relu(v.w, s.y, s.w);
                    a[mb] = v;
                }
                #pragma unroll
                for (int nb2 = 0; nb2 < 2; nb2++) {
                    uint4 bv = Bf[(ks * 8 + jb + nb2) * 32 + lid];
                    const uint32_t* b = (const uint32_t*)&bv;
                    mma16816h(acc[0][2*nb2],   (const uint32_t*)&a[0], b);
                    mma16816h(acc[1][2*nb2],   (const uint32_t*)&a[1], b);
                    mma16816h(acc[0][2*nb2+1], (const uint32_t*)&a[0], b+2);
                    mma16816h(acc[1][2*nb2+1], (const uint32_t*)&a[1], b+2);
                }
            }

            __syncthreads();   // all warps' h1 fragment reads done before h2 overwrite
            EPILOGUE(t);
        }
    }

    // ---- stats: reduce over gid (xor-shuffles), then shared, then global ----
    #pragma unroll
    for (int q = 0; q < 4; q++) {
        float2 a = up2(s1v[q]), b = up2(s2v[q]);
        #pragma unroll
        for (int msk = 4; msk <= 16; msk <<= 1) {
            a.x += __shfl_xor_sync(0xffffffffu, a.x, msk);
            a.y += __shfl_xor_sync(0xffffffffu, a.y, msk);
            b.x += __shfl_xor_sync(0xffffffffu, b.x, msk);
            b.y += __shfl_xor_sync(0xffffffffu, b.y, msk);
        }
        if (gid == 0) {
            int c0 = n0 + (q >> 1) * 16 + (q & 1) * 8 + 2 * tig;
            atomicAdd(&sRed1[c0], a.x);  atomicAdd(&sRed1[c0+1], a.y);
            atomicAdd(&sRed2[c0], b.x);  atomicAdd(&sRed2[c0+1], b.y);
        }
    }
    __syncthreads();
    if (tid < C) {
        atomicAdd((PASS == 1 ? g_sum1 : g_sum2) + tid, sRed1[tid]);
        atomicAdd((PASS == 1 ? g_sq1 : g_sq2) + tid, sRed2[tid]);
    }
}

__global__ void k_fin(const float* __restrict__ g, const float* __restrict__ be, int which) {
    int c = threadIdx.x;
    float sum = which ? g_sum2[c] : g_sum1[c];
    float sq  = which ? g_sq2[c]  : g_sq1[c];
    float mean = sum * (1.f / E_EDGES);
    float var  = sq * (1.f / E_EDGES) - mean * mean;
    float a = g[c] * rsqrtf(var + BN_EPS);
    float cc = be[c] - mean * a;
    if (which) { g_a2[c] = a; g_c2[c] = cc; }
    else       { g_a1[c] = a; g_c1[c] = cc; }
}

// classifier on fragment-major h2: one warp per (t, mi) block of 16 edges
__global__ __launch_bounds__(256) void k_out(const float* __restrict__ wc,
                                             const float* __restrict__ bc,
                                             float* __restrict__ out)
{
    __shared__ uint4 sScSh[32];
    __shared__ uint2 sWc[32];
    const int tid = threadIdx.x;
    const int lid = tid & 31;
    const int gid = lid >> 2;
    const int tig = lid & 3;

    if (tid < 32) {
        int ks = tid >> 2, tg = tid & 3;
        int cl = ks * 16 + 2 * tg, ch = cl + 8;
        sScSh[tid] = make_uint4(pack_h2(g_a2[cl], g_a2[cl + 1]),
                                pack_h2(g_a2[ch], g_a2[ch + 1]),
                                pack_h2(g_c2[cl], g_c2[cl + 1]),
                                pack_h2(g_c2[ch], g_c2[ch + 1]));
        sWc[tid] = make_uint2(pack_h2(wc[cl], wc[cl + 1]), pack_h2(wc[ch], wc[ch + 1]));
    }
    __syncthreads();

    const float b = bc[0];
    const int warp_g = blockIdx.x * 8 + (tid >> 5);
    const int nwarp = gridDim.x * 8;
    const int NU = NTILES * 4;   // 62500 blocks of 16 edges

    for (int u = warp_g; u < NU; u += nwarp) {
        float a0 = 0.f, a1 = 0.f;
        #pragma unroll
        for (int ks = 0; ks < 8; ks++) {
            uint4 v = g_h4[(size_t)(u*8 + ks)*32 + lid];
            uint4 s = sScSh[ks * 4 + tig];
            uint2 w = sWc[ks * 4 + tig];
            uint32_t h0 = hfma2relu(v.x, s.x, s.z);
            uint32_t h1 = hfma2relu(v.y, s.x, s.z);
            uint32_t h2 = hfma2relu(v.z, s.y, s.w);
            uint32_t h3 = hfma2relu(v.w, s.y, s.w);
            float2 p;
            p = unpack_h2(hmul2u(h0, w.x));  a0 += p.x + p.y;
            p = unpack_h2(hmul2u(h2, w.y));  a0 += p.x + p.y;
            p = unpack_h2(hmul2u(h1, w.x));  a1 += p.x + p.y;
            p = unpack_h2(hmul2u(h3, w.y));  a1 += p.x + p.y;
        }
        a0 += __shfl_xor_sync(0xffffffffu, a0, 1);
        a0 += __shfl_xor_sync(0xffffffffu, a0, 2);
        a1 += __shfl_xor_sync(0xffffffffu, a1, 1);
        a1 += __shfl_xor_sync(0xffffffffu, a1, 2);
        if (tig == 0) {
            out[u * 16 + gid]     = a0 + b;
            out[u * 16 + gid + 8] = a1 + b;
        }
    }
}

extern "C" void kernel_launch(void* const* d_in, const int* in_sizes, int n_in,
                              void* d_out, int out_size) {
    const float* x     = (const float*)d_in[0];
    const void*  edges = d_in[1];
    const float* w1    = (const float*)d_in[2];
    const float* b1    = (const float*)d_in[3];
    const float* g1    = (const float*)d_in[4];
    const float* be1   = (const float*)d_in[5];
    const float* w2    = (const float*)d_in[6];
    const float* b2    = (const float*)d_in[7];
    const float* g2    = (const float*)d_in[8];
    const float* be2   = (const float*)d_in[9];
    const float* wc    = (const float*)d_in[10];
    const float* bc    = (const float*)d_in[11];
    float* out = (float*)d_out;
    (void)in_sizes; (void)n_in; (void)out_size;

    cudaFuncSetAttribute(k_pass_mma<1>, cudaFuncAttributeMaxDynamicSharedMemorySize, SM_TOTAL);
    cudaFuncSetAttribute(k_pass_mma<2>, cudaFuncAttributeMaxDynamicSharedMemorySize, SM_TOTAL);

    k_quant<<<2048, 256>>>(x);
    k_prep<<<16, 256>>>((const unsigned*)edges, w1, w2);
    k_pass_mma<1><<<296, 256, SM_TOTAL>>>(edges, b1);
    k_fin<<<1, 128>>>(g1, be1, 0);
    k_pass_mma<2><<<296, 256, SM_TOTAL>>>(edges, b2);
    k_fin<<<1, 128>>>(g2, be2, 1);
    k_out<<<2048, 256>>>(wc, bc, out);
}